// round 3
// baseline (speedup 1.0000x reference)
#include <cuda_runtime.h>
#include <math.h>

#define BATCH 8
#define CCH   64
#define HH    128
#define WWD   128
#define HWN   (HH*WWD)            // 16384
#define NEXP  3
#define NHEAD 16
#define NHID  16
#define OUTM  (BATCH*CCH*HWN)     // 8388608

typedef unsigned long long ull;

// ---------------- scratch (static device globals; no runtime allocs) ----
__device__ float g_part[BATCH][32][4160];     // per-chunk partial Gram (4096) + channel sums (64)
__device__ float g_G[BATCH][4096];            // Gram matrices
__device__ float g_M1[BATCH][NEXP][4096];     // A @ Wv  (per batch, expert)
__device__ float g_R[BATCH][CCH][576];        // collapsed conv weights, layout [b][cin][tap*64+cout]
__device__ float g_logit[BATCH][NEXP];

// ---------------- packed fp32x2 helpers --------------------------------
__device__ __forceinline__ ull dup2(float f) {
    ull r; unsigned u = __float_as_uint(f);
    asm("mov.b64 %0, {%1,%2};" : "=l"(r) : "r"(u), "r"(u));
    return r;
}
#define FMA2(acc, a, b) asm("fma.rn.f32x2 %0, %1, %2, %0;" : "+l"(acc) : "l"(a), "l"(b))

// =========================================================================
// K1: partial Gram G_b = sum_p x[:,p] x[:,p]^T over a 512-pixel chunk,
//     plus per-channel partial sums. grid (32, 8), 256 threads. f32x2.
// =========================================================================
__global__ __launch_bounds__(256) void k_gram(const float* __restrict__ x) {
    int b = blockIdx.y, chunk = blockIdx.x;
    __shared__ __align__(16) float xs[64 * 68];   // [pixel][channel], stride 68
    int t  = threadIdx.x;
    int lc = t >> 2;              // load channel
    int lp = (t & 3) * 16;        // load pixel offset within 64-subtile
    int i0 = (t & 15) * 4;        // Gram tile row base
    int j0 = (t >> 4) * 4;        // Gram tile col base

    ull accp[8];                  // [ii][jpair], pairs (j0,j0+1),(j0+2,j0+3)
#pragma unroll
    for (int k = 0; k < 8; k++) accp[k] = 0ULL;
    float csum = 0.f;

    const float* xb = x + (size_t)b * CCH * HWN;
    int base = chunk * 512;

    for (int st = 0; st < 8; st++) {
        const float4* xp = reinterpret_cast<const float4*>(xb + lc * HWN + base + st * 64 + lp);
        float4 v0 = xp[0], v1 = xp[1], v2 = xp[2], v3 = xp[3];
        float tmp[16] = {v0.x, v0.y, v0.z, v0.w, v1.x, v1.y, v1.z, v1.w,
                         v2.x, v2.y, v2.z, v2.w, v3.x, v3.y, v3.z, v3.w};
#pragma unroll
        for (int i = 0; i < 16; i++) {
            csum += tmp[i];
            xs[(lp + i) * 68 + lc] = tmp[i];
        }
        __syncthreads();
#pragma unroll 8
        for (int p = 0; p < 64; p++) {
            float4 a = *reinterpret_cast<const float4*>(&xs[p * 68 + i0]);
            ulonglong2 bp = *reinterpret_cast<const ulonglong2*>(&xs[p * 68 + j0]);
            ull d0 = dup2(a.x), d1 = dup2(a.y), d2 = dup2(a.z), d3 = dup2(a.w);
            FMA2(accp[0], d0, bp.x);  FMA2(accp[1], d0, bp.y);
            FMA2(accp[2], d1, bp.x);  FMA2(accp[3], d1, bp.y);
            FMA2(accp[4], d2, bp.x);  FMA2(accp[5], d2, bp.y);
            FMA2(accp[6], d3, bp.x);  FMA2(accp[7], d3, bp.y);
        }
        __syncthreads();
    }

    float* gp = g_part[b][chunk];
#pragma unroll
    for (int ii = 0; ii < 4; ii++) {
        *reinterpret_cast<ull*>(&gp[(i0 + ii) * 64 + j0])     = accp[ii * 2];
        *reinterpret_cast<ull*>(&gp[(i0 + ii) * 64 + j0 + 2]) = accp[ii * 2 + 1];
    }

    csum += __shfl_xor_sync(0xffffffffu, csum, 1);
    csum += __shfl_xor_sync(0xffffffffu, csum, 2);
    if ((t & 3) == 0) gp[4096 + lc] = csum;
}

// =========================================================================
// K2: grid (17, 8). parts 0..15 reduce G slices in parallel; part 16 does
//     mean + routing MLP (gelu, relu) + tail outputs.
// =========================================================================
__global__ __launch_bounds__(256) void k_route(const float* __restrict__ hidden,
                                               const float* __restrict__ r1w,
                                               const float* __restrict__ r1b,
                                               const float* __restrict__ r3w,
                                               const float* __restrict__ r3b,
                                               float* __restrict__ out, int out_size) {
    int part = blockIdx.x, b = blockIdx.y, t = threadIdx.x;
    if (part < 16) {
        int idx = part * 256 + t;
        float s0 = 0.f, s1 = 0.f, s2 = 0.f, s3 = 0.f;
#pragma unroll
        for (int ch = 0; ch < 32; ch += 4) {
            s0 += g_part[b][ch][idx];
            s1 += g_part[b][ch + 1][idx];
            s2 += g_part[b][ch + 2][idx];
            s3 += g_part[b][ch + 3][idx];
        }
        g_G[b][idx] = (s0 + s1) + (s2 + s3);
        return;
    }
    __shared__ float mean[64];
    __shared__ float hg[16];
    if (t < 64) {
        float s = 0.f;
#pragma unroll
        for (int ch = 0; ch < 32; ch++) s += g_part[b][ch][4096 + t];
        mean[t] = s * (1.0f / 16384.0f);
    }
    __syncthreads();
    if (t < 16) {
        float h = r1b[t];
        for (int c = 0; c < 64; c++) h = fmaf(mean[c], r1w[t * 80 + c], h);
        for (int j = 0; j < 16; j++) h = fmaf(hidden[b * 16 + j], r1w[t * 80 + 64 + j], h);
        float g = 0.5f * h * (1.0f + erff(h * 0.70710678118654752f));
        hg[t] = g;
        int oi = OUTM + b * 16 + t;
        if (oi < out_size) out[oi] = g;
    }
    __syncthreads();
    if (t < 3) {
        float v = r3b[t];
        for (int j = 0; j < 16; j++) v = fmaf(hg[j], r3w[t * 16 + j], v);
        v = fmaxf(v, 0.f);
        g_logit[b][t] = v;
        int oi = OUTM + 128 + b * 3 + t;
        if (oi < out_size) out[oi] = v;
    }
}

// =========================================================================
// K3: grid (3, 8, 4). Each block handles 4 heads (16 channel rows):
//     tq/tk via Gram trick, norms, scores, softmax, M1 = A @ Wv.
// =========================================================================
__global__ __launch_bounds__(256) void k_attn(const float* __restrict__ qkvw,
                                              const float* __restrict__ temp) {
    int e = blockIdx.x, b = blockIdx.y, hq = blockIdx.z;
    int r0 = hq * 16;                          // first channel row of this block
    __shared__ __align__(16) float Gs[4096];
    __shared__ __align__(16) float tqs[1024];
    __shared__ __align__(16) float tks[1024];
    __shared__ __align__(16) float Wq16[1024];
    __shared__ __align__(16) float Wk16[1024];
    __shared__ float Sraw[64], nq[16], nk[16], A[64];

    int t = threadIdx.x;
    const float* Wq = qkvw + (size_t)e * 192 * 64;
    const float* Wk = Wq + 4096;
    const float* Wv = Wq + 8192;

#pragma unroll
    for (int k = 0; k < 16; k++) Gs[t + 256 * k] = g_G[b][t + 256 * k];
#pragma unroll
    for (int k = 0; k < 4; k++) {
        int idx = t + 256 * k;
        Wq16[idx] = Wq[r0 * 64 + idx];
        Wk16[idx] = Wk[r0 * 64 + idx];
    }
    __syncthreads();

    int ir = t >> 4;            // local row 0..15
    int c0 = (t & 15) * 4;      // column group

    // tq = Wq@G, tk = Wk@G (rows r0..r0+15 only)
    {
        float aq0 = 0.f, aq1 = 0.f, aq2 = 0.f, aq3 = 0.f;
        float ak0 = 0.f, ak1 = 0.f, ak2 = 0.f, ak3 = 0.f;
#pragma unroll 4
        for (int m = 0; m < 64; m++) {
            float wq = Wq16[ir * 64 + m];
            float wk = Wk16[ir * 64 + m];
            float4 g = *reinterpret_cast<const float4*>(&Gs[m * 64 + c0]);
            aq0 = fmaf(wq, g.x, aq0); aq1 = fmaf(wq, g.y, aq1);
            aq2 = fmaf(wq, g.z, aq2); aq3 = fmaf(wq, g.w, aq3);
            ak0 = fmaf(wk, g.x, ak0); ak1 = fmaf(wk, g.y, ak1);
            ak2 = fmaf(wk, g.z, ak2); ak3 = fmaf(wk, g.w, ak3);
        }
        *reinterpret_cast<float4*>(&tqs[ir * 64 + c0]) = make_float4(aq0, aq1, aq2, aq3);
        *reinterpret_cast<float4*>(&tks[ir * 64 + c0]) = make_float4(ak0, ak1, ak2, ak3);
    }
    __syncthreads();

    // dots: Sraw (64 entries), nq (16), nk (16)
    if (t < 64) {
        int h = t >> 4, a = (t >> 2) & 3, b2 = t & 3;
        int qi = h * 4 + a, kj = h * 4 + b2;
        float s = 0.f;
#pragma unroll 4
        for (int c = 0; c < 64; c += 4) {
            float4 u = *reinterpret_cast<const float4*>(&tqs[qi * 64 + c]);
            float4 w = *reinterpret_cast<const float4*>(&Wk16[kj * 64 + c]);
            s = fmaf(u.x, w.x, s); s = fmaf(u.y, w.y, s);
            s = fmaf(u.z, w.z, s); s = fmaf(u.w, w.w, s);
        }
        Sraw[t] = s;
    } else if (t < 80) {
        int lr = t - 64;
        float s = 0.f;
#pragma unroll 4
        for (int c = 0; c < 64; c += 4) {
            float4 u = *reinterpret_cast<const float4*>(&tqs[lr * 64 + c]);
            float4 w = *reinterpret_cast<const float4*>(&Wq16[lr * 64 + c]);
            s = fmaf(u.x, w.x, s); s = fmaf(u.y, w.y, s);
            s = fmaf(u.z, w.z, s); s = fmaf(u.w, w.w, s);
        }
        nq[lr] = s;
    } else if (t < 96) {
        int lr = t - 80;
        float s = 0.f;
#pragma unroll 4
        for (int c = 0; c < 64; c += 4) {
            float4 u = *reinterpret_cast<const float4*>(&tks[lr * 64 + c]);
            float4 w = *reinterpret_cast<const float4*>(&Wk16[lr * 64 + c]);
            s = fmaf(u.x, w.x, s); s = fmaf(u.y, w.y, s);
            s = fmaf(u.z, w.z, s); s = fmaf(u.w, w.w, s);
        }
        nk[lr] = s;
    }
    __syncthreads();

    // softmax (16 local rows)
    if (t < 16) {
        int hl = t >> 2, a = t & 3;
        float qn = fmaxf(sqrtf(nq[t]), 1e-12f);
        float tp = __ldg(&temp[e * 16 + hq * 4 + hl]);
        float v[4];
        float mx = -1e30f;
#pragma unroll
        for (int j = 0; j < 4; j++) {
            float kn = fmaxf(sqrtf(nk[hl * 4 + j]), 1e-12f);
            v[j] = Sraw[hl * 16 + a * 4 + j] / (qn * kn) * tp;
            mx = fmaxf(mx, v[j]);
        }
        float s = 0.f;
#pragma unroll
        for (int j = 0; j < 4; j++) { v[j] = expf(v[j] - mx); s += v[j]; }
        float inv = 1.0f / s;
#pragma unroll
        for (int j = 0; j < 4; j++) A[t * 4 + j] = v[j] * inv;
    }
    __syncthreads();

    // M1[gi][c] = sum_j A[ir][j] * Wv[row_base+j][c]
    {
        int gi = r0 + ir;
        int hb = r0 + (ir >> 2) * 4;
        float a0 = A[ir * 4], a1 = A[ir * 4 + 1], a2 = A[ir * 4 + 2], a3 = A[ir * 4 + 3];
        float4 w0 = *reinterpret_cast<const float4*>(&Wv[(hb + 0) * 64 + c0]);
        float4 w1 = *reinterpret_cast<const float4*>(&Wv[(hb + 1) * 64 + c0]);
        float4 w2 = *reinterpret_cast<const float4*>(&Wv[(hb + 2) * 64 + c0]);
        float4 w3 = *reinterpret_cast<const float4*>(&Wv[(hb + 3) * 64 + c0]);
        float4 o;
        o.x = fmaf(a3, w3.x, fmaf(a2, w2.x, fmaf(a1, w1.x, a0 * w0.x)));
        o.y = fmaf(a3, w3.y, fmaf(a2, w2.y, fmaf(a1, w1.y, a0 * w0.y)));
        o.z = fmaf(a3, w3.z, fmaf(a2, w2.z, fmaf(a1, w1.z, a0 * w0.z)));
        o.w = fmaf(a3, w3.w, fmaf(a2, w2.w, fmaf(a1, w1.w, a0 * w0.w)));
        *reinterpret_cast<float4*>(&g_M1[b][e][gi * 64 + c0]) = o;
    }
}

// =========================================================================
// K4: R_t[o][c] = sum_e logit * sum_m P_e[o][m] * dw_e[m][t] * M1_e[m][c]
//     grid (9, 8), 256 threads. All operands staged through shared.
// =========================================================================
__global__ __launch_bounds__(256) void k_buildR(const float* __restrict__ projw,
                                                const float* __restrict__ dww) {
    int tap = blockIdx.x, b = blockIdx.y, t = threadIdx.x;
    __shared__ float M1s[4096];
    __shared__ float PsT[64 * 65];   // [m][o] padded to kill bank conflicts
    __shared__ float wds[64];
    int o  = t & 63;
    int c0 = (t >> 6) * 16;
    float acc[16];
#pragma unroll
    for (int cc = 0; cc < 16; cc++) acc[cc] = 0.f;

    for (int e = 0; e < 3; e++) {
        __syncthreads();
#pragma unroll
        for (int k = 0; k < 16; k++) {
            int idx = t + 256 * k;
            M1s[idx] = g_M1[b][e][idx];
            int oo = idx >> 6, mm = idx & 63;
            PsT[mm * 65 + oo] = projw[(size_t)e * 4096 + idx];
        }
        if (t < 64) wds[t] = dww[(size_t)e * 576 + t * 9 + tap];
        __syncthreads();
        float l = g_logit[b][e];
#pragma unroll 4
        for (int m = 0; m < 64; m++) {
            float coef = l * PsT[m * 65 + o] * wds[m];
            const float* mm = &M1s[m * 64 + c0];
#pragma unroll
            for (int cc = 0; cc < 16; cc++) acc[cc] = fmaf(coef, mm[cc], acc[cc]);
        }
    }
#pragma unroll
    for (int cc = 0; cc < 16; cc++) g_R[b][c0 + cc][tap * 64 + o] = acc[cc];
}

// =========================================================================
// K5: main fused kernel (f32x2). out[b] = per-batch dense 3x3 conv 64->64.
//     Block: (2 rows x 128 cols) x 64 oc; thread: 4 oc x 8 pixel-pairs.
//     Even pairs come from sx; odd pairs from sxo (x shifted by one col);
//     R weights stored pre-duplicated in sRdu for direct u64 broadcast.
// =========================================================================
__global__ __launch_bounds__(256, 2) void k_conv(const float* __restrict__ x,
                                                 float* __restrict__ out) {
    int b  = blockIdx.y;
    int y0 = blockIdx.x * 2;
    __shared__ __align__(16) float sx[4 * 132];   // cols -1..128 at idx 0..129
    __shared__ __align__(16) float sxo[4 * 132];  // sxo[c] = sx[c+1] (image col c)
    __shared__ __align__(16) ull  sRdu[576];      // duplicated R values

    int t   = threadIdx.x;
    int oG  = t >> 4;          // 0..15 -> out-channel group of 4
    int pos = t & 15;
    int ty  = pos >> 3;        // 0..1
    int x0  = (pos & 7) * 16;  // 0..112
    int y   = y0 + ty;

    const float* xb = x + (size_t)b * 64 * HWN;
    const float* Rb = &g_R[b][0][0];

    // cooperative-load index precompute (sx: 520 elems; 3 legs)
    int li1 = t + 256, li2 = t + 512;
    int lr0 = t / 130,   lc0v = t % 130;
    int lr1 = li1 / 130, lc1v = li1 % 130;
    int lr2 = li2 / 130, lc2v = li2 % 130;
    int gy0 = y0 - 1 + lr0, gx0 = lc0v - 1;
    int gy1 = y0 - 1 + lr1, gx1 = lc1v - 1;
    int gy2 = y0 - 1 + lr2, gx2 = lc2v - 1;
    bool v0 = (gy0 >= 0 && gy0 < 128 && gx0 >= 0 && gx0 < 128);
    bool v1 = (gy1 >= 0 && gy1 < 128 && gx1 >= 0 && gx1 < 128);
    bool x2ok = (li2 < 520);
    bool v2 = x2ok && (gy2 >= 0 && gy2 < 128 && gx2 >= 0 && gx2 < 128);
    int off0 = gy0 * 128 + gx0;
    int off1 = gy1 * 128 + gx1;
    int off2 = gy2 * 128 + gx2;
    bool rv2 = (t + 512) < 576;

    ull acc[4][8];
#pragma unroll
    for (int a = 0; a < 4; a++)
#pragma unroll
        for (int q = 0; q < 8; q++) acc[a][q] = 0ULL;

    // prefetch c = 0
    float px0 = v0 ? __ldg(&xb[off0]) : 0.f;
    float px1 = v1 ? __ldg(&xb[off1]) : 0.f;
    float px2 = v2 ? __ldg(&xb[off2]) : 0.f;
    float pr0 = __ldg(&Rb[t]);
    float pr1 = __ldg(&Rb[t + 256]);
    float pr2 = rv2 ? __ldg(&Rb[t + 512]) : 0.f;

    for (int c = 0; c < 64; c++) {
        __syncthreads();
        sx[lr0 * 132 + lc0v] = px0;
        if (lc0v > 0) sxo[lr0 * 132 + lc0v - 1] = px0;
        sx[lr1 * 132 + lc1v] = px1;
        if (lc1v > 0) sxo[lr1 * 132 + lc1v - 1] = px1;
        if (x2ok) {
            sx[lr2 * 132 + lc2v] = px2;
            if (lc2v > 0) sxo[lr2 * 132 + lc2v - 1] = px2;
        }
        sRdu[t]       = dup2(pr0);
        sRdu[t + 256] = dup2(pr1);
        if (rv2) sRdu[t + 512] = dup2(pr2);
        __syncthreads();

        if (c + 1 < 64) {
            const float* xc = xb + (size_t)(c + 1) * HWN;
            px0 = v0 ? __ldg(&xc[off0]) : 0.f;
            px1 = v1 ? __ldg(&xc[off1]) : 0.f;
            px2 = v2 ? __ldg(&xc[off2]) : 0.f;
            const float* rc = Rb + (size_t)(c + 1) * 576;
            pr0 = __ldg(&rc[t]);
            pr1 = __ldg(&rc[t + 256]);
            pr2 = rv2 ? __ldg(&rc[t + 512]) : 0.f;
        }

#pragma unroll
        for (int ky = 0; ky < 3; ky++) {
            const float* srow  = &sx[(ty + ky) * 132 + x0];
            const float* srowo = &sxo[(ty + ky) * 132 + x0];
            ull pe[9], po[8];
#pragma unroll
            for (int q = 0; q < 4; q++) {
                ulonglong2 v = *reinterpret_cast<const ulonglong2*>(srow + q * 4);
                pe[2 * q] = v.x; pe[2 * q + 1] = v.y;
            }
            pe[8] = *reinterpret_cast<const ull*>(srow + 16);
#pragma unroll
            for (int q = 0; q < 4; q++) {
                ulonglong2 v = *reinterpret_cast<const ulonglong2*>(srowo + q * 4);
                po[2 * q] = v.x; po[2 * q + 1] = v.y;
            }
#pragma unroll
            for (int o4 = 0; o4 < 4; o4++) {
                int oc = oG * 4 + o4;
                ull r0 = sRdu[(ky * 3 + 0) * 64 + oc];
                ull r1 = sRdu[(ky * 3 + 1) * 64 + oc];
                ull r2 = sRdu[(ky * 3 + 2) * 64 + oc];
#pragma unroll
                for (int q = 0; q < 8; q++) {
                    FMA2(acc[o4][q], r0, pe[q]);
                    FMA2(acc[o4][q], r1, po[q]);
                    FMA2(acc[o4][q], r2, pe[q + 1]);
                }
            }
        }
    }

#pragma unroll
    for (int o4 = 0; o4 < 4; o4++) {
        float* op = out + (((size_t)b * 64 + oG * 4 + o4) * 128 + y) * 128 + x0;
#pragma unroll
        for (int q2 = 0; q2 < 4; q2++) {
            ulonglong2 v;
            v.x = acc[o4][2 * q2];
            v.y = acc[o4][2 * q2 + 1];
            *reinterpret_cast<ulonglong2*>(op + q2 * 4) = v;
        }
    }
}

// =========================================================================
extern "C" void kernel_launch(void* const* d_in, const int* in_sizes, int n_in,
                              void* d_out, int out_size) {
    const float* x      = (const float*)d_in[0];
    const float* hidden = (const float*)d_in[1];
    const float* qkvw   = (const float*)d_in[2];
    const float* dww    = (const float*)d_in[3];
    const float* projw  = (const float*)d_in[4];
    const float* temp   = (const float*)d_in[5];
    const float* r1w    = (const float*)d_in[6];
    const float* r1b    = (const float*)d_in[7];
    const float* r3w    = (const float*)d_in[8];
    const float* r3b    = (const float*)d_in[9];
    float* out = (float*)d_out;

    k_gram<<<dim3(32, 8), 256>>>(x);
    k_route<<<dim3(17, 8), 256>>>(hidden, r1w, r1b, r3w, r3b, out, out_size);
    k_attn<<<dim3(3, 8, 4), 256>>>(qkvw, temp);
    k_buildR<<<dim3(9, 8), 256>>>(projw, dww);
    k_conv<<<dim3(64, 8), 256>>>(x, out);
}

// round 4
// speedup vs baseline: 1.6313x; 1.6313x over previous
#include <cuda_runtime.h>
#include <math.h>

#define BATCH 8
#define CCH   64
#define HH    128
#define WWD   128
#define HWN   (HH*WWD)            // 16384
#define NEXP  3
#define NHEAD 16
#define NHID  16
#define OUTM  (BATCH*CCH*HWN)     // 8388608

// ---------------- scratch (static device globals; no runtime allocs) ----
__device__ float g_part[BATCH][32][4160];     // per-chunk partial Gram (4096) + channel sums (64)
__device__ float g_G[BATCH][4096];            // Gram matrices
__device__ float g_M1[BATCH][NEXP][4096];     // A @ Wv  (per batch, expert)
__device__ float g_R[BATCH][CCH][576];        // collapsed conv weights, layout [b][cin][tap*64+cout]
__device__ float g_logit[BATCH][NEXP];

// =========================================================================
// K1: partial Gram G_b = sum_p x[:,p] x[:,p]^T over a 512-pixel chunk,
//     plus per-channel partial sums. grid (32, 8), 256 threads. (R2 scalar)
// =========================================================================
__global__ __launch_bounds__(256) void k_gram(const float* __restrict__ x) {
    int b = blockIdx.y, chunk = blockIdx.x;
    __shared__ __align__(16) float xs[64 * 68];   // [pixel][channel], stride 68
    int t  = threadIdx.x;
    int lc = t >> 2;              // load channel
    int lp = (t & 3) * 16;        // load pixel offset within 64-subtile
    int i0 = (t & 15) * 4;        // Gram tile row base
    int j0 = (t >> 4) * 4;        // Gram tile col base

    float acc[16];
#pragma unroll
    for (int k = 0; k < 16; k++) acc[k] = 0.f;
    float csum = 0.f;

    const float* xb = x + (size_t)b * CCH * HWN;
    int base = chunk * 512;

    for (int st = 0; st < 8; st++) {
        const float4* xp = reinterpret_cast<const float4*>(xb + lc * HWN + base + st * 64 + lp);
        float4 v0 = xp[0], v1 = xp[1], v2 = xp[2], v3 = xp[3];
        float tmp[16] = {v0.x, v0.y, v0.z, v0.w, v1.x, v1.y, v1.z, v1.w,
                         v2.x, v2.y, v2.z, v2.w, v3.x, v3.y, v3.z, v3.w};
#pragma unroll
        for (int i = 0; i < 16; i++) {
            csum += tmp[i];
            xs[(lp + i) * 68 + lc] = tmp[i];
        }
        __syncthreads();
#pragma unroll 8
        for (int p = 0; p < 64; p++) {
            float4 a  = *reinterpret_cast<const float4*>(&xs[p * 68 + i0]);
            float4 bb = *reinterpret_cast<const float4*>(&xs[p * 68 + j0]);
            acc[0]  = fmaf(a.x, bb.x, acc[0]);   acc[1]  = fmaf(a.x, bb.y, acc[1]);
            acc[2]  = fmaf(a.x, bb.z, acc[2]);   acc[3]  = fmaf(a.x, bb.w, acc[3]);
            acc[4]  = fmaf(a.y, bb.x, acc[4]);   acc[5]  = fmaf(a.y, bb.y, acc[5]);
            acc[6]  = fmaf(a.y, bb.z, acc[6]);   acc[7]  = fmaf(a.y, bb.w, acc[7]);
            acc[8]  = fmaf(a.z, bb.x, acc[8]);   acc[9]  = fmaf(a.z, bb.y, acc[9]);
            acc[10] = fmaf(a.z, bb.z, acc[10]);  acc[11] = fmaf(a.z, bb.w, acc[11]);
            acc[12] = fmaf(a.w, bb.x, acc[12]);  acc[13] = fmaf(a.w, bb.y, acc[13]);
            acc[14] = fmaf(a.w, bb.z, acc[14]);  acc[15] = fmaf(a.w, bb.w, acc[15]);
        }
        __syncthreads();
    }

    float* gp = g_part[b][chunk];
#pragma unroll
    for (int ii = 0; ii < 4; ii++)
#pragma unroll
        for (int jj = 0; jj < 4; jj++)
            gp[(i0 + ii) * 64 + (j0 + jj)] = acc[ii * 4 + jj];

    csum += __shfl_xor_sync(0xffffffffu, csum, 1);
    csum += __shfl_xor_sync(0xffffffffu, csum, 2);
    if ((t & 3) == 0) gp[4096 + lc] = csum;
}

// =========================================================================
// K2: grid (17, 8). parts 0..15 reduce G slices in parallel; part 16 does
//     mean + routing MLP (gelu, relu) + tail outputs.
// =========================================================================
__global__ __launch_bounds__(256) void k_route(const float* __restrict__ hidden,
                                               const float* __restrict__ r1w,
                                               const float* __restrict__ r1b,
                                               const float* __restrict__ r3w,
                                               const float* __restrict__ r3b,
                                               float* __restrict__ out, int out_size) {
    int part = blockIdx.x, b = blockIdx.y, t = threadIdx.x;
    if (part < 16) {
        int idx = part * 256 + t;
        float s0 = 0.f, s1 = 0.f, s2 = 0.f, s3 = 0.f;
#pragma unroll
        for (int ch = 0; ch < 32; ch += 4) {
            s0 += g_part[b][ch][idx];
            s1 += g_part[b][ch + 1][idx];
            s2 += g_part[b][ch + 2][idx];
            s3 += g_part[b][ch + 3][idx];
        }
        g_G[b][idx] = (s0 + s1) + (s2 + s3);
        return;
    }
    __shared__ float mean[64];
    __shared__ float hg[16];
    if (t < 64) {
        float s = 0.f;
#pragma unroll
        for (int ch = 0; ch < 32; ch++) s += g_part[b][ch][4096 + t];
        mean[t] = s * (1.0f / 16384.0f);
    }
    __syncthreads();
    if (t < 16) {
        float h = r1b[t];
        for (int c = 0; c < 64; c++) h = fmaf(mean[c], r1w[t * 80 + c], h);
        for (int j = 0; j < 16; j++) h = fmaf(hidden[b * 16 + j], r1w[t * 80 + 64 + j], h);
        float g = 0.5f * h * (1.0f + erff(h * 0.70710678118654752f));
        hg[t] = g;
        int oi = OUTM + b * 16 + t;
        if (oi < out_size) out[oi] = g;
    }
    __syncthreads();
    if (t < 3) {
        float v = r3b[t];
        for (int j = 0; j < 16; j++) v = fmaf(hg[j], r3w[t * 16 + j], v);
        v = fmaxf(v, 0.f);
        g_logit[b][t] = v;
        int oi = OUTM + 128 + b * 3 + t;
        if (oi < out_size) out[oi] = v;
    }
}

// =========================================================================
// K3: grid (3, 8, 4). Each block handles 4 heads (16 channel rows):
//     tq/tk via Gram trick, norms, scores, softmax, M1 = A @ Wv.
// =========================================================================
__global__ __launch_bounds__(256) void k_attn(const float* __restrict__ qkvw,
                                              const float* __restrict__ temp) {
    int e = blockIdx.x, b = blockIdx.y, hq = blockIdx.z;
    int r0 = hq * 16;                          // first channel row of this block
    __shared__ __align__(16) float Gs[4096];
    __shared__ __align__(16) float tqs[1024];
    __shared__ __align__(16) float tks[1024];
    __shared__ __align__(16) float Wq16[1024];
    __shared__ __align__(16) float Wk16[1024];
    __shared__ float Sraw[64], nq[16], nk[16], A[64];

    int t = threadIdx.x;
    const float* Wq = qkvw + (size_t)e * 192 * 64;
    const float* Wk = Wq + 4096;
    const float* Wv = Wq + 8192;

#pragma unroll
    for (int k = 0; k < 16; k++) Gs[t + 256 * k] = g_G[b][t + 256 * k];
#pragma unroll
    for (int k = 0; k < 4; k++) {
        int idx = t + 256 * k;
        Wq16[idx] = Wq[r0 * 64 + idx];
        Wk16[idx] = Wk[r0 * 64 + idx];
    }
    __syncthreads();

    int ir = t >> 4;            // local row 0..15
    int c0 = (t & 15) * 4;      // column group

    // tq = Wq@G, tk = Wk@G (rows r0..r0+15 only)
    {
        float aq0 = 0.f, aq1 = 0.f, aq2 = 0.f, aq3 = 0.f;
        float ak0 = 0.f, ak1 = 0.f, ak2 = 0.f, ak3 = 0.f;
#pragma unroll 4
        for (int m = 0; m < 64; m++) {
            float wq = Wq16[ir * 64 + m];
            float wk = Wk16[ir * 64 + m];
            float4 g = *reinterpret_cast<const float4*>(&Gs[m * 64 + c0]);
            aq0 = fmaf(wq, g.x, aq0); aq1 = fmaf(wq, g.y, aq1);
            aq2 = fmaf(wq, g.z, aq2); aq3 = fmaf(wq, g.w, aq3);
            ak0 = fmaf(wk, g.x, ak0); ak1 = fmaf(wk, g.y, ak1);
            ak2 = fmaf(wk, g.z, ak2); ak3 = fmaf(wk, g.w, ak3);
        }
        *reinterpret_cast<float4*>(&tqs[ir * 64 + c0]) = make_float4(aq0, aq1, aq2, aq3);
        *reinterpret_cast<float4*>(&tks[ir * 64 + c0]) = make_float4(ak0, ak1, ak2, ak3);
    }
    __syncthreads();

    // dots: Sraw (64 entries), nq (16), nk (16)
    if (t < 64) {
        int h = t >> 4, a = (t >> 2) & 3, b2 = t & 3;
        int qi = h * 4 + a, kj = h * 4 + b2;
        float s = 0.f;
#pragma unroll 4
        for (int c = 0; c < 64; c += 4) {
            float4 u = *reinterpret_cast<const float4*>(&tqs[qi * 64 + c]);
            float4 w = *reinterpret_cast<const float4*>(&Wk16[kj * 64 + c]);
            s = fmaf(u.x, w.x, s); s = fmaf(u.y, w.y, s);
            s = fmaf(u.z, w.z, s); s = fmaf(u.w, w.w, s);
        }
        Sraw[t] = s;
    } else if (t < 80) {
        int lr = t - 64;
        float s = 0.f;
#pragma unroll 4
        for (int c = 0; c < 64; c += 4) {
            float4 u = *reinterpret_cast<const float4*>(&tqs[lr * 64 + c]);
            float4 w = *reinterpret_cast<const float4*>(&Wq16[lr * 64 + c]);
            s = fmaf(u.x, w.x, s); s = fmaf(u.y, w.y, s);
            s = fmaf(u.z, w.z, s); s = fmaf(u.w, w.w, s);
        }
        nq[lr] = s;
    } else if (t < 96) {
        int lr = t - 80;
        float s = 0.f;
#pragma unroll 4
        for (int c = 0; c < 64; c += 4) {
            float4 u = *reinterpret_cast<const float4*>(&tks[lr * 64 + c]);
            float4 w = *reinterpret_cast<const float4*>(&Wk16[lr * 64 + c]);
            s = fmaf(u.x, w.x, s); s = fmaf(u.y, w.y, s);
            s = fmaf(u.z, w.z, s); s = fmaf(u.w, w.w, s);
        }
        nk[lr] = s;
    }
    __syncthreads();

    // softmax (16 local rows)
    if (t < 16) {
        int hl = t >> 2, a = t & 3;
        float qn = fmaxf(sqrtf(nq[t]), 1e-12f);
        float tp = __ldg(&temp[e * 16 + hq * 4 + hl]);
        float v[4];
        float mx = -1e30f;
#pragma unroll
        for (int j = 0; j < 4; j++) {
            float kn = fmaxf(sqrtf(nk[hl * 4 + j]), 1e-12f);
            v[j] = Sraw[hl * 16 + a * 4 + j] / (qn * kn) * tp;
            mx = fmaxf(mx, v[j]);
        }
        float s = 0.f;
#pragma unroll
        for (int j = 0; j < 4; j++) { v[j] = expf(v[j] - mx); s += v[j]; }
        float inv = 1.0f / s;
#pragma unroll
        for (int j = 0; j < 4; j++) A[t * 4 + j] = v[j] * inv;
    }
    __syncthreads();

    // M1[gi][c] = sum_j A[ir][j] * Wv[row_base+j][c]
    {
        int gi = r0 + ir;
        int hb = r0 + (ir >> 2) * 4;
        float a0 = A[ir * 4], a1 = A[ir * 4 + 1], a2 = A[ir * 4 + 2], a3 = A[ir * 4 + 3];
        float4 w0 = *reinterpret_cast<const float4*>(&Wv[(hb + 0) * 64 + c0]);
        float4 w1 = *reinterpret_cast<const float4*>(&Wv[(hb + 1) * 64 + c0]);
        float4 w2 = *reinterpret_cast<const float4*>(&Wv[(hb + 2) * 64 + c0]);
        float4 w3 = *reinterpret_cast<const float4*>(&Wv[(hb + 3) * 64 + c0]);
        float4 o;
        o.x = fmaf(a3, w3.x, fmaf(a2, w2.x, fmaf(a1, w1.x, a0 * w0.x)));
        o.y = fmaf(a3, w3.y, fmaf(a2, w2.y, fmaf(a1, w1.y, a0 * w0.y)));
        o.z = fmaf(a3, w3.z, fmaf(a2, w2.z, fmaf(a1, w1.z, a0 * w0.z)));
        o.w = fmaf(a3, w3.w, fmaf(a2, w2.w, fmaf(a1, w1.w, a0 * w0.w)));
        *reinterpret_cast<float4*>(&g_M1[b][e][gi * 64 + c0]) = o;
    }
}

// =========================================================================
// K4: R_t[o][c] = sum_e logit * sum_m P_e[o][m] * dw_e[m][t] * M1_e[m][c]
//     grid (9, 8), 256 threads. All operands staged through shared.
// =========================================================================
__global__ __launch_bounds__(256) void k_buildR(const float* __restrict__ projw,
                                                const float* __restrict__ dww) {
    int tap = blockIdx.x, b = blockIdx.y, t = threadIdx.x;
    __shared__ float M1s[4096];
    __shared__ float PsT[64 * 65];   // [m][o] padded to kill bank conflicts
    __shared__ float wds[64];
    int o  = t & 63;
    int c0 = (t >> 6) * 16;
    float acc[16];
#pragma unroll
    for (int cc = 0; cc < 16; cc++) acc[cc] = 0.f;

    for (int e = 0; e < 3; e++) {
        __syncthreads();
#pragma unroll
        for (int k = 0; k < 16; k++) {
            int idx = t + 256 * k;
            M1s[idx] = g_M1[b][e][idx];
            int oo = idx >> 6, mm = idx & 63;
            PsT[mm * 65 + oo] = projw[(size_t)e * 4096 + idx];
        }
        if (t < 64) wds[t] = dww[(size_t)e * 576 + t * 9 + tap];
        __syncthreads();
        float l = g_logit[b][e];
#pragma unroll 4
        for (int m = 0; m < 64; m++) {
            float coef = l * PsT[m * 65 + o] * wds[m];
            const float* mm = &M1s[m * 64 + c0];
#pragma unroll
            for (int cc = 0; cc < 16; cc++) acc[cc] = fmaf(coef, mm[cc], acc[cc]);
        }
    }
#pragma unroll
    for (int cc = 0; cc < 16; cc++) g_R[b][c0 + cc][tap * 64 + o] = acc[cc];
}

// =========================================================================
// K5: main fused kernel (Round-2 scalar version, ~roofline for FFMA).
//     out[b] = per-batch dense 3x3 conv 64->64, SAME padding.
//     Block: (2 rows x 128 cols) x 64 oc; thread: 4 oc x 16 px.
// =========================================================================
__global__ __launch_bounds__(256, 2) void k_conv(const float* __restrict__ x,
                                                 float* __restrict__ out) {
    int b  = blockIdx.y;
    int y0 = blockIdx.x * 2;
    __shared__ __align__(16) float sx[4 * 132];   // rows y0-1..y0+2, cols -1..128 at idx 0..129
    __shared__ float sR[576];

    int t   = threadIdx.x;
    int oG  = t >> 4;          // 0..15 -> out-channel group of 4
    int pos = t & 15;
    int ty  = pos >> 3;        // 0..1
    int x0  = (pos & 7) * 16;  // 0..112
    int y   = y0 + ty;

    const float* xb = x + (size_t)b * 64 * HWN;
    const float* Rb = &g_R[b][0][0];   // [c][576]

    // cooperative-load index precompute (sx: 520 useful elems; 3 legs)
    int li1 = t + 256, li2 = t + 512;
    int lr0 = t / 130,   lc0v = t % 130;
    int lr1 = li1 / 130, lc1v = li1 % 130;
    int lr2 = li2 / 130, lc2v = li2 % 130;
    int gy0 = y0 - 1 + lr0, gx0 = lc0v - 1;
    int gy1 = y0 - 1 + lr1, gx1 = lc1v - 1;
    int gy2 = y0 - 1 + lr2, gx2 = lc2v - 1;
    bool v0 = (gy0 >= 0 && gy0 < 128 && gx0 >= 0 && gx0 < 128);
    bool v1 = (gy1 >= 0 && gy1 < 128 && gx1 >= 0 && gx1 < 128);
    bool x2ok = (li2 < 520);
    bool v2 = x2ok && (gy2 >= 0 && gy2 < 128 && gx2 >= 0 && gx2 < 128);
    int off0 = gy0 * 128 + gx0;
    int off1 = gy1 * 128 + gx1;
    int off2 = gy2 * 128 + gx2;
    bool rv2 = (t + 512) < 576;

    float acc[4][16];
#pragma unroll
    for (int a = 0; a < 4; a++)
#pragma unroll
        for (int p = 0; p < 16; p++) acc[a][p] = 0.f;

    // prefetch c = 0
    float px0 = v0 ? __ldg(&xb[off0]) : 0.f;
    float px1 = v1 ? __ldg(&xb[off1]) : 0.f;
    float px2 = v2 ? __ldg(&xb[off2]) : 0.f;
    float pr0 = __ldg(&Rb[t]);
    float pr1 = __ldg(&Rb[t + 256]);
    float pr2 = rv2 ? __ldg(&Rb[t + 512]) : 0.f;

    for (int c = 0; c < 64; c++) {
        __syncthreads();
        sx[lr0 * 132 + lc0v] = px0;
        sx[lr1 * 132 + lc1v] = px1;
        if (x2ok) sx[lr2 * 132 + lc2v] = px2;
        sR[t] = pr0;
        sR[t + 256] = pr1;
        if (rv2) sR[t + 512] = pr2;
        __syncthreads();

        if (c + 1 < 64) {
            const float* xc = xb + (size_t)(c + 1) * HWN;
            px0 = v0 ? __ldg(&xc[off0]) : 0.f;
            px1 = v1 ? __ldg(&xc[off1]) : 0.f;
            px2 = v2 ? __ldg(&xc[off2]) : 0.f;
            const float* rc = Rb + (size_t)(c + 1) * 576;
            pr0 = __ldg(&rc[t]);
            pr1 = __ldg(&rc[t + 256]);
            pr2 = rv2 ? __ldg(&rc[t + 512]) : 0.f;
        }

#pragma unroll
        for (int ky = 0; ky < 3; ky++) {
            const float* srow = &sx[(ty + ky) * 132 + x0];
            float xr[18];
#pragma unroll
            for (int q = 0; q < 4; q++) {
                float4 v = *reinterpret_cast<const float4*>(srow + q * 4);
                xr[q * 4] = v.x; xr[q * 4 + 1] = v.y; xr[q * 4 + 2] = v.z; xr[q * 4 + 3] = v.w;
            }
            xr[16] = srow[16];
            xr[17] = srow[17];
#pragma unroll
            for (int o4 = 0; o4 < 4; o4++) {
#pragma unroll
                for (int kx = 0; kx < 3; kx++) {
                    float r = sR[(ky * 3 + kx) * 64 + oG * 4 + o4];
#pragma unroll
                    for (int px = 0; px < 16; px++)
                        acc[o4][px] = fmaf(r, xr[px + kx], acc[o4][px]);
                }
            }
        }
    }

#pragma unroll
    for (int o4 = 0; o4 < 4; o4++) {
        float* op = out + (((size_t)b * 64 + oG * 4 + o4) * 128 + y) * 128 + x0;
#pragma unroll
        for (int q = 0; q < 4; q++) {
            float4 v = make_float4(acc[o4][q * 4], acc[o4][q * 4 + 1],
                                   acc[o4][q * 4 + 2], acc[o4][q * 4 + 3]);
            *reinterpret_cast<float4*>(op + q * 4) = v;
        }
    }
}

// =========================================================================
extern "C" void kernel_launch(void* const* d_in, const int* in_sizes, int n_in,
                              void* d_out, int out_size) {
    const float* x      = (const float*)d_in[0];
    const float* hidden = (const float*)d_in[1];
    const float* qkvw   = (const float*)d_in[2];
    const float* dww    = (const float*)d_in[3];
    const float* projw  = (const float*)d_in[4];
    const float* temp   = (const float*)d_in[5];
    const float* r1w    = (const float*)d_in[6];
    const float* r1b    = (const float*)d_in[7];
    const float* r3w    = (const float*)d_in[8];
    const float* r3b    = (const float*)d_in[9];
    float* out = (float*)d_out;

    k_gram<<<dim3(32, 8), 256>>>(x);
    k_route<<<dim3(17, 8), 256>>>(hidden, r1w, r1b, r3w, r3b, out, out_size);
    k_attn<<<dim3(3, 8, 4), 256>>>(qkvw, temp);
    k_buildR<<<dim3(9, 8), 256>>>(projw, dww);
    k_conv<<<dim3(64, 8), 256>>>(x, out);
}

// round 6
// speedup vs baseline: 3.0344x; 1.8601x over previous
#include <cuda_runtime.h>
#include <cuda_bf16.h>
#include <math.h>
#include <stdint.h>

#define BATCH 8
#define CCH   64
#define HH    128
#define WWD   128
#define HWN   (HH*WWD)            // 16384
#define NEXP  3
#define NHEAD 16
#define NHID  16
#define OUTM  (BATCH*CCH*HWN)     // 8388608

// ---------------- scratch (static device globals; no runtime allocs) ----
__device__ float g_part[BATCH][32][4160];     // per-chunk partial Gram (4096) + channel sums (64)
__device__ float g_G[BATCH][4096];            // Gram matrices
__device__ float g_M1[BATCH][NEXP][4096];     // A @ Wv  (per batch, expert)
__device__ float g_logit[BATCH][NEXP];
// collapsed conv weights as bf16 hi/lo planes, layout [b][tap][plane][o*64+c]
__device__ __align__(16) __nv_bfloat16 g_Bt[BATCH][9][2][4096];

// ---------------- mma.sync helpers (baseline PTX, sm_80+) ---------------
__device__ __forceinline__ void mma_bf16(float* c, const uint32_t* a,
                                         uint32_t b0, uint32_t b1) {
    asm volatile("mma.sync.aligned.m16n8k16.row.col.f32.bf16.bf16.f32 "
        "{%0,%1,%2,%3}, {%4,%5,%6,%7}, {%8,%9}, {%0,%1,%2,%3};"
        : "+f"(c[0]), "+f"(c[1]), "+f"(c[2]), "+f"(c[3])
        : "r"(a[0]), "r"(a[1]), "r"(a[2]), "r"(a[3]), "r"(b0), "r"(b1));
}
// split a float2 into packed bf16x2 hi (truncation) and lo (residual, rn)
__device__ __forceinline__ void split2(float fx, float fy, uint32_t& hi, uint32_t& lo) {
    uint32_t u0 = __float_as_uint(fx), u1 = __float_as_uint(fy);
    uint32_t h;
    asm("prmt.b32 %0, %1, %2, 0x7632;" : "=r"(h) : "r"(u0), "r"(u1));
    float l0 = fx - __uint_as_float(u0 & 0xffff0000u);
    float l1 = fy - __uint_as_float(u1 & 0xffff0000u);
    uint32_t l;
    asm("cvt.rn.bf16x2.f32 %0, %1, %2;" : "=r"(l) : "f"(l1), "f"(l0));
    hi = h; lo = l;
}

// smem layout for k_convmma (bytes)
#define T_STRIDE  66                           // floats per (ri,p) row
#define T_BYTES   (520 * T_STRIDE * 4)         // 137280
#define BS_OFF    T_BYTES
#define BS_ROW    144                          // bytes per oc row (72 halves)
#define BS_PLANE  (64 * BS_ROW)                // 9216
#define SM_TOTAL  (BS_OFF + 2 * BS_PLANE)      // 155712
#define DS_STRIDE 268                          // floats per oc row in output stage

// =========================================================================
// K1: partial Gram G_b = sum_p x[:,p] x[:,p]^T over a 512-pixel chunk,
//     plus per-channel partial sums. grid (32, 8), 256 threads.
// =========================================================================
__global__ __launch_bounds__(256) void k_gram(const float* __restrict__ x) {
    int b = blockIdx.y, chunk = blockIdx.x;
    __shared__ __align__(16) float xs[64 * 68];
    int t  = threadIdx.x;
    int lc = t >> 2;
    int lp = (t & 3) * 16;
    int i0 = (t & 15) * 4;
    int j0 = (t >> 4) * 4;

    float acc[16];
#pragma unroll
    for (int k = 0; k < 16; k++) acc[k] = 0.f;
    float csum = 0.f;

    const float* xb = x + (size_t)b * CCH * HWN;
    int base = chunk * 512;

    for (int st = 0; st < 8; st++) {
        const float4* xp = reinterpret_cast<const float4*>(xb + lc * HWN + base + st * 64 + lp);
        float4 v0 = xp[0], v1 = xp[1], v2 = xp[2], v3 = xp[3];
        float tmp[16] = {v0.x, v0.y, v0.z, v0.w, v1.x, v1.y, v1.z, v1.w,
                         v2.x, v2.y, v2.z, v2.w, v3.x, v3.y, v3.z, v3.w};
#pragma unroll
        for (int i = 0; i < 16; i++) {
            csum += tmp[i];
            xs[(lp + i) * 68 + lc] = tmp[i];
        }
        __syncthreads();
#pragma unroll 8
        for (int p = 0; p < 64; p++) {
            float4 a  = *reinterpret_cast<const float4*>(&xs[p * 68 + i0]);
            float4 bb = *reinterpret_cast<const float4*>(&xs[p * 68 + j0]);
            acc[0]  = fmaf(a.x, bb.x, acc[0]);   acc[1]  = fmaf(a.x, bb.y, acc[1]);
            acc[2]  = fmaf(a.x, bb.z, acc[2]);   acc[3]  = fmaf(a.x, bb.w, acc[3]);
            acc[4]  = fmaf(a.y, bb.x, acc[4]);   acc[5]  = fmaf(a.y, bb.y, acc[5]);
            acc[6]  = fmaf(a.y, bb.z, acc[6]);   acc[7]  = fmaf(a.y, bb.w, acc[7]);
            acc[8]  = fmaf(a.z, bb.x, acc[8]);   acc[9]  = fmaf(a.z, bb.y, acc[9]);
            acc[10] = fmaf(a.z, bb.z, acc[10]);  acc[11] = fmaf(a.z, bb.w, acc[11]);
            acc[12] = fmaf(a.w, bb.x, acc[12]);  acc[13] = fmaf(a.w, bb.y, acc[13]);
            acc[14] = fmaf(a.w, bb.z, acc[14]);  acc[15] = fmaf(a.w, bb.w, acc[15]);
        }
        __syncthreads();
    }

    float* gp = g_part[b][chunk];
#pragma unroll
    for (int ii = 0; ii < 4; ii++)
#pragma unroll
        for (int jj = 0; jj < 4; jj++)
            gp[(i0 + ii) * 64 + (j0 + jj)] = acc[ii * 4 + jj];

    csum += __shfl_xor_sync(0xffffffffu, csum, 1);
    csum += __shfl_xor_sync(0xffffffffu, csum, 2);
    if ((t & 3) == 0) gp[4096 + lc] = csum;
}

// =========================================================================
// K2: grid (17, 8). parts 0..15 reduce G slices; part 16: mean + MLP.
// =========================================================================
__global__ __launch_bounds__(256) void k_route(const float* __restrict__ hidden,
                                               const float* __restrict__ r1w,
                                               const float* __restrict__ r1b,
                                               const float* __restrict__ r3w,
                                               const float* __restrict__ r3b,
                                               float* __restrict__ out, int out_size) {
    int part = blockIdx.x, b = blockIdx.y, t = threadIdx.x;
    if (part < 16) {
        int idx = part * 256 + t;
        float s0 = 0.f, s1 = 0.f, s2 = 0.f, s3 = 0.f;
#pragma unroll
        for (int ch = 0; ch < 32; ch += 4) {
            s0 += g_part[b][ch][idx];
            s1 += g_part[b][ch + 1][idx];
            s2 += g_part[b][ch + 2][idx];
            s3 += g_part[b][ch + 3][idx];
        }
        g_G[b][idx] = (s0 + s1) + (s2 + s3);
        return;
    }
    __shared__ float mean[64];
    __shared__ float hg[16];
    if (t < 64) {
        float s = 0.f;
#pragma unroll
        for (int ch = 0; ch < 32; ch++) s += g_part[b][ch][4096 + t];
        mean[t] = s * (1.0f / 16384.0f);
    }
    __syncthreads();
    if (t < 16) {
        float h = r1b[t];
        for (int c = 0; c < 64; c++) h = fmaf(mean[c], r1w[t * 80 + c], h);
        for (int j = 0; j < 16; j++) h = fmaf(hidden[b * 16 + j], r1w[t * 80 + 64 + j], h);
        float g = 0.5f * h * (1.0f + erff(h * 0.70710678118654752f));
        hg[t] = g;
        int oi = OUTM + b * 16 + t;
        if (oi < out_size) out[oi] = g;
    }
    __syncthreads();
    if (t < 3) {
        float v = r3b[t];
        for (int j = 0; j < 16; j++) v = fmaf(hg[j], r3w[t * 16 + j], v);
        v = fmaxf(v, 0.f);
        g_logit[b][t] = v;
        int oi = OUTM + 128 + b * 3 + t;
        if (oi < out_size) out[oi] = v;
    }
}

// =========================================================================
// K3: grid (3, 8, 4). 4 heads per block: Gram trick, softmax, M1 = A @ Wv.
// =========================================================================
__global__ __launch_bounds__(256) void k_attn(const float* __restrict__ qkvw,
                                              const float* __restrict__ temp) {
    int e = blockIdx.x, b = blockIdx.y, hq = blockIdx.z;
    int r0 = hq * 16;
    __shared__ __align__(16) float Gs[4096];
    __shared__ __align__(16) float tqs[1024];
    __shared__ __align__(16) float tks[1024];
    __shared__ __align__(16) float Wq16[1024];
    __shared__ __align__(16) float Wk16[1024];
    __shared__ float Sraw[64], nq[16], nk[16], A[64];

    int t = threadIdx.x;
    const float* Wq = qkvw + (size_t)e * 192 * 64;
    const float* Wk = Wq + 4096;
    const float* Wv = Wq + 8192;

#pragma unroll
    for (int k = 0; k < 16; k++) Gs[t + 256 * k] = g_G[b][t + 256 * k];
#pragma unroll
    for (int k = 0; k < 4; k++) {
        int idx = t + 256 * k;
        Wq16[idx] = Wq[r0 * 64 + idx];
        Wk16[idx] = Wk[r0 * 64 + idx];
    }
    __syncthreads();

    int ir = t >> 4;
    int c0 = (t & 15) * 4;

    {
        float aq0 = 0.f, aq1 = 0.f, aq2 = 0.f, aq3 = 0.f;
        float ak0 = 0.f, ak1 = 0.f, ak2 = 0.f, ak3 = 0.f;
#pragma unroll 4
        for (int m = 0; m < 64; m++) {
            float wq = Wq16[ir * 64 + m];
            float wk = Wk16[ir * 64 + m];
            float4 g = *reinterpret_cast<const float4*>(&Gs[m * 64 + c0]);
            aq0 = fmaf(wq, g.x, aq0); aq1 = fmaf(wq, g.y, aq1);
            aq2 = fmaf(wq, g.z, aq2); aq3 = fmaf(wq, g.w, aq3);
            ak0 = fmaf(wk, g.x, ak0); ak1 = fmaf(wk, g.y, ak1);
            ak2 = fmaf(wk, g.z, ak2); ak3 = fmaf(wk, g.w, ak3);
        }
        *reinterpret_cast<float4*>(&tqs[ir * 64 + c0]) = make_float4(aq0, aq1, aq2, aq3);
        *reinterpret_cast<float4*>(&tks[ir * 64 + c0]) = make_float4(ak0, ak1, ak2, ak3);
    }
    __syncthreads();

    if (t < 64) {
        int h = t >> 4, a = (t >> 2) & 3, b2 = t & 3;
        int qi = h * 4 + a, kj = h * 4 + b2;
        float s = 0.f;
#pragma unroll 4
        for (int c = 0; c < 64; c += 4) {
            float4 u = *reinterpret_cast<const float4*>(&tqs[qi * 64 + c]);
            float4 w = *reinterpret_cast<const float4*>(&Wk16[kj * 64 + c]);
            s = fmaf(u.x, w.x, s); s = fmaf(u.y, w.y, s);
            s = fmaf(u.z, w.z, s); s = fmaf(u.w, w.w, s);
        }
        Sraw[t] = s;
    } else if (t < 80) {
        int lr = t - 64;
        float s = 0.f;
#pragma unroll 4
        for (int c = 0; c < 64; c += 4) {
            float4 u = *reinterpret_cast<const float4*>(&tqs[lr * 64 + c]);
            float4 w = *reinterpret_cast<const float4*>(&Wq16[lr * 64 + c]);
            s = fmaf(u.x, w.x, s); s = fmaf(u.y, w.y, s);
            s = fmaf(u.z, w.z, s); s = fmaf(u.w, w.w, s);
        }
        nq[lr] = s;
    } else if (t < 96) {
        int lr = t - 80;
        float s = 0.f;
#pragma unroll 4
        for (int c = 0; c < 64; c += 4) {
            float4 u = *reinterpret_cast<const float4*>(&tks[lr * 64 + c]);
            float4 w = *reinterpret_cast<const float4*>(&Wk16[lr * 64 + c]);
            s = fmaf(u.x, w.x, s); s = fmaf(u.y, w.y, s);
            s = fmaf(u.z, w.z, s); s = fmaf(u.w, w.w, s);
        }
        nk[lr] = s;
    }
    __syncthreads();

    if (t < 16) {
        int hl = t >> 2, a = t & 3;
        float qn = fmaxf(sqrtf(nq[t]), 1e-12f);
        float tp = __ldg(&temp[e * 16 + hq * 4 + hl]);
        float v[4];
        float mx = -1e30f;
#pragma unroll
        for (int j = 0; j < 4; j++) {
            float kn = fmaxf(sqrtf(nk[hl * 4 + j]), 1e-12f);
            v[j] = Sraw[hl * 16 + a * 4 + j] / (qn * kn) * tp;
            mx = fmaxf(mx, v[j]);
        }
        float s = 0.f;
#pragma unroll
        for (int j = 0; j < 4; j++) { v[j] = expf(v[j] - mx); s += v[j]; }
        float inv = 1.0f / s;
#pragma unroll
        for (int j = 0; j < 4; j++) A[t * 4 + j] = v[j] * inv;
    }
    __syncthreads();

    {
        int gi = r0 + ir;
        int hb = r0 + (ir >> 2) * 4;
        float a0 = A[ir * 4], a1 = A[ir * 4 + 1], a2 = A[ir * 4 + 2], a3 = A[ir * 4 + 3];
        float4 w0 = *reinterpret_cast<const float4*>(&Wv[(hb + 0) * 64 + c0]);
        float4 w1 = *reinterpret_cast<const float4*>(&Wv[(hb + 1) * 64 + c0]);
        float4 w2 = *reinterpret_cast<const float4*>(&Wv[(hb + 2) * 64 + c0]);
        float4 w3 = *reinterpret_cast<const float4*>(&Wv[(hb + 3) * 64 + c0]);
        float4 o;
        o.x = fmaf(a3, w3.x, fmaf(a2, w2.x, fmaf(a1, w1.x, a0 * w0.x)));
        o.y = fmaf(a3, w3.y, fmaf(a2, w2.y, fmaf(a1, w1.y, a0 * w0.y)));
        o.z = fmaf(a3, w3.z, fmaf(a2, w2.z, fmaf(a1, w1.z, a0 * w0.z)));
        o.w = fmaf(a3, w3.w, fmaf(a2, w2.w, fmaf(a1, w1.w, a0 * w0.w)));
        *reinterpret_cast<float4*>(&g_M1[b][e][gi * 64 + c0]) = o;
    }
}

// =========================================================================
// K4: build collapsed conv weights; emit bf16 hi/lo planes in Bt[n=o][k=c]
//     layout for the warp-MMA conv. grid (9, 8), 256 threads.
// =========================================================================
__global__ __launch_bounds__(256) void k_buildR(const float* __restrict__ projw,
                                                const float* __restrict__ dww) {
    int tap = blockIdx.x, b = blockIdx.y, t = threadIdx.x;
    __shared__ float M1s[4096];
    __shared__ float PsT[64 * 65];
    __shared__ float wds[64];
    int o  = t & 63;
    int c0 = (t >> 6) * 16;
    float acc[16];
#pragma unroll
    for (int cc = 0; cc < 16; cc++) acc[cc] = 0.f;

    for (int e = 0; e < 3; e++) {
        __syncthreads();
#pragma unroll
        for (int k = 0; k < 16; k++) {
            int idx = t + 256 * k;
            M1s[idx] = g_M1[b][e][idx];
            int oo = idx >> 6, mm = idx & 63;
            PsT[mm * 65 + oo] = projw[(size_t)e * 4096 + idx];
        }
        if (t < 64) wds[t] = dww[(size_t)e * 576 + t * 9 + tap];
        __syncthreads();
        float l = g_logit[b][e];
#pragma unroll 4
        for (int m = 0; m < 64; m++) {
            float coef = l * PsT[m * 65 + o] * wds[m];
            const float* mm = &M1s[m * 64 + c0];
#pragma unroll
            for (int cc = 0; cc < 16; cc++) acc[cc] = fmaf(coef, mm[cc], acc[cc]);
        }
    }
    __nv_bfloat16* bh = &g_Bt[b][tap][0][0];
    __nv_bfloat16* bl = &g_Bt[b][tap][1][0];
#pragma unroll
    for (int cc = 0; cc < 16; cc++) {
        int c = c0 + cc;
        float v = acc[cc];
        __nv_bfloat16 hi = __float2bfloat16(v);
        __nv_bfloat16 lo = __float2bfloat16(v - __bfloat162float(hi));
        bh[o * 64 + c] = hi;
        bl[o * 64 + c] = lo;
    }
}

// =========================================================================
// K5: warp-MMA conv (mma.sync m16n8k16 bf16, hi/lo 3-term split).
//     Block = 2 image rows (256 px) x 64 oc; 8 warps, warp tile 32x64.
//     grid (64, 8), 256 threads, dyn smem ~152 KB.
// =========================================================================
__global__ __launch_bounds__(256) void k_convmma(const float* __restrict__ x,
                                                 float* __restrict__ out) {
    extern __shared__ __align__(16) char smem[];
    float* T = reinterpret_cast<float*>(smem);

    const int tid = threadIdx.x;
    const int b = blockIdx.y;
    const int y0 = blockIdx.x * 2;

    // stage x rows y0-1..y0+2, px -1..128, 64 ch into T[(ri*130+p)*66 + c]
    const float* xb = x + (size_t)b * 64 * HWN;
    for (int idx = tid; idx < 4 * 130 * 64; idx += 256) {
        int p = idx % 130;
        int rest = idx / 130;
        int c = rest & 63, ri = rest >> 6;
        int gr = y0 - 1 + ri, gp = p - 1;
        float v = 0.f;
        if ((unsigned)gr < 128u && (unsigned)gp < 128u)
            v = __ldg(&xb[(size_t)c * HWN + gr * 128 + gp]);
        T[(ri * 130 + p) * T_STRIDE + c] = v;
    }

    const int w = tid >> 5, lane = tid & 31;
    const int g = lane >> 2, tg = lane & 3;
    const int wrow = w >> 2, wcol = (w & 3) * 32;

    float acc[2][8][4];
#pragma unroll
    for (int s = 0; s < 2; s++)
#pragma unroll
        for (int j = 0; j < 8; j++)
#pragma unroll
            for (int r = 0; r < 4; r++) acc[s][j][r] = 0.f;

    const uint32_t* Bg = reinterpret_cast<const uint32_t*>(&g_Bt[b][0][0][0]);

    for (int tap = 0; tap < 9; tap++) {
        int dy = tap / 3, dx = tap % 3;
        __syncthreads();   // T staged (tap 0) / previous tap's B consumed
        // stage B planes for this tap: Bs[plane][o-row(72h)][c]
#pragma unroll
        for (int i = 0; i < 16; i++) {
            int idx = tid + i * 256;                // 0..4095 uint32 words
            int plane = idx >> 11;
            int rem = idx & 2047;
            int row = rem >> 5, u = rem & 31;
            uint32_t v = __ldg(&Bg[(size_t)tap * 4096 + idx]);
            *reinterpret_cast<uint32_t*>(smem + BS_OFF + plane * BS_PLANE + row * BS_ROW + u * 4) = v;
        }
        __syncthreads();

        int ri0 = wrow + dy;
#pragma unroll
        for (int kc = 0; kc < 4; kc++) {
            int c0 = kc * 16;
            uint32_t ahi[2][4], alo[2][4];
#pragma unroll
            for (int s = 0; s < 2; s++) {
                int p0 = wcol + s * 16 + g + dx;
                int base0 = (ri0 * 130 + p0) * T_STRIDE + c0 + tg * 2;
                float2 f0 = *reinterpret_cast<const float2*>(&T[base0]);
                float2 f1 = *reinterpret_cast<const float2*>(&T[base0 + 8 * T_STRIDE]);
                float2 f2 = *reinterpret_cast<const float2*>(&T[base0 + 8]);
                float2 f3 = *reinterpret_cast<const float2*>(&T[base0 + 8 * T_STRIDE + 8]);
                split2(f0.x, f0.y, ahi[s][0], alo[s][0]);
                split2(f1.x, f1.y, ahi[s][1], alo[s][1]);
                split2(f2.x, f2.y, ahi[s][2], alo[s][2]);
                split2(f3.x, f3.y, ahi[s][3], alo[s][3]);
            }
#pragma unroll
            for (int j = 0; j < 8; j++) {
                const char* brow = smem + BS_OFF + (j * 8 + g) * BS_ROW + (c0 + tg * 2) * 2;
                uint32_t bh0 = *reinterpret_cast<const uint32_t*>(brow);
                uint32_t bh1 = *reinterpret_cast<const uint32_t*>(brow + 16);
                uint32_t bl0 = *reinterpret_cast<const uint32_t*>(brow + BS_PLANE);
                uint32_t bl1 = *reinterpret_cast<const uint32_t*>(brow + BS_PLANE + 16);
#pragma unroll
                for (int s = 0; s < 2; s++) {
                    mma_bf16(acc[s][j], ahi[s], bh0, bh1);
                    mma_bf16(acc[s][j], ahi[s], bl0, bl1);
                    mma_bf16(acc[s][j], alo[s], bh0, bh1);
                }
            }
        }
    }
    __syncthreads();   // all warps done reading T -> reuse as Ds

    // scatter accs to Ds[oc][px] (stride 268, conflict-free)
    float* Ds = reinterpret_cast<float*>(smem);
#pragma unroll
    for (int s = 0; s < 2; s++) {
        int px = wrow * 128 + wcol + s * 16 + g;
#pragma unroll
        for (int j = 0; j < 8; j++) {
            int oc = j * 8 + tg * 2;
            Ds[oc * DS_STRIDE + px]           = acc[s][j][0];
            Ds[(oc + 1) * DS_STRIDE + px]     = acc[s][j][1];
            Ds[oc * DS_STRIDE + px + 8]       = acc[s][j][2];
            Ds[(oc + 1) * DS_STRIDE + px + 8] = acc[s][j][3];
        }
    }
    __syncthreads();

    // coalesced float4 stores
    float* ob = out + (size_t)b * 64 * HWN;
#pragma unroll
    for (int i = 0; i < 16; i++) {
        int idx = tid + i * 256;
        int oc = idx >> 6, f4 = idx & 63;
        int px = f4 * 4;
        float4 v = *reinterpret_cast<const float4*>(&Ds[oc * DS_STRIDE + px]);
        int yy = y0 + (px >> 7), xx = px & 127;
        *reinterpret_cast<float4*>(&ob[((size_t)oc * 128 + yy) * 128 + xx]) = v;
    }
}

// =========================================================================
extern "C" void kernel_launch(void* const* d_in, const int* in_sizes, int n_in,
                              void* d_out, int out_size) {
    const float* x      = (const float*)d_in[0];
    const float* hidden = (const float*)d_in[1];
    const float* qkvw   = (const float*)d_in[2];
    const float* dww    = (const float*)d_in[3];
    const float* projw  = (const float*)d_in[4];
    const float* temp   = (const float*)d_in[5];
    const float* r1w    = (const float*)d_in[6];
    const float* r1b    = (const float*)d_in[7];
    const float* r3w    = (const float*)d_in[8];
    const float* r3b    = (const float*)d_in[9];
    float* out = (float*)d_out;

    cudaFuncSetAttribute(k_convmma, cudaFuncAttributeMaxDynamicSharedMemorySize,
                         SM_TOTAL);

    k_gram<<<dim3(32, 8), 256>>>(x);
    k_route<<<dim3(17, 8), 256>>>(hidden, r1w, r1b, r3w, r3b, out, out_size);
    k_attn<<<dim3(3, 8, 4), 256>>>(qkvw, temp);
    k_buildR<<<dim3(9, 8), 256>>>(projw, dww);
    k_convmma<<<dim3(64, 8), 256, SM_TOTAL>>>(x, out);
}

// round 7
// speedup vs baseline: 3.7899x; 1.2490x over previous
#include <cuda_runtime.h>
#include <cuda_bf16.h>
#include <math.h>
#include <stdint.h>

#define BATCH 8
#define CCH   64
#define HH    128
#define WWD   128
#define HWN   (HH*WWD)            // 16384
#define NEXP  3
#define NHEAD 16
#define NHID  16
#define OUTM  (BATCH*CCH*HWN)     // 8388608

// ---------------- scratch (static device globals; no runtime allocs) ----
__device__ float g_part[BATCH][32][4160];     // partial Gram slots (4096) + channel sums (64)
__device__ float g_G[BATCH][4096];            // Gram matrices
__device__ float g_M1[BATCH][NEXP][4096];     // A @ Wv  (per batch, expert)
__device__ float g_logit[BATCH][NEXP];
// collapsed conv weights as bf16 hi/lo planes, layout [b][tap][plane][o*64+c]
__device__ __align__(16) __nv_bfloat16 g_Bt[BATCH][9][2][4096];

// ---------------- mma.sync helpers (baseline PTX, sm_80+) ---------------
__device__ __forceinline__ void mma_bf16(float* c, const uint32_t* a,
                                         uint32_t b0, uint32_t b1) {
    asm volatile("mma.sync.aligned.m16n8k16.row.col.f32.bf16.bf16.f32 "
        "{%0,%1,%2,%3}, {%4,%5,%6,%7}, {%8,%9}, {%0,%1,%2,%3};"
        : "+f"(c[0]), "+f"(c[1]), "+f"(c[2]), "+f"(c[3])
        : "r"(a[0]), "r"(a[1]), "r"(a[2]), "r"(a[3]), "r"(b0), "r"(b1));
}
// split a float2 into packed bf16x2 hi (truncation) and lo (residual, rn)
__device__ __forceinline__ void split2(float fx, float fy, uint32_t& hi, uint32_t& lo) {
    uint32_t u0 = __float_as_uint(fx), u1 = __float_as_uint(fy);
    uint32_t h;
    asm("prmt.b32 %0, %1, %2, 0x7632;" : "=r"(h) : "r"(u0), "r"(u1));
    float l0 = fx - __uint_as_float(u0 & 0xffff0000u);
    float l1 = fy - __uint_as_float(u1 & 0xffff0000u);
    uint32_t l;
    asm("cvt.rn.bf16x2.f32 %0, %1, %2;" : "=r"(l) : "f"(l1), "f"(l0));
    hi = h; lo = l;
}

// ---------------- smem layouts --------------------------------------
// k_gram: 2 planes of [64 ch][132 words] bf16x2
#define GX_WORDS (64 * 132)                    // 8448 words/plane
#define GSM_TOTAL (2 * GX_WORDS * 4)           // 67584 B
// k_convmma: T hi/lo planes (520 plins x 72 halves) + B buffer
#define TW_STRIDE 36                           // u32 words per plin
#define T_PLANE_B (520 * 72 * 2)               // 74880 B per plane
#define BS_OFF    (2 * T_PLANE_B)              // 149760
#define BS_WORDS  2304                         // words per plane (64 rows x 36)
#define SM_TOTAL  (BS_OFF + 2 * BS_WORDS * 4)  // 168192
#define DS_STRIDE 268

// =========================================================================
// K1: Gram via warp-MMA. grid (16, 8), 256 threads. Each block: 1024-px
//     chunk, 4 k-steps of 256 px. 8 warps = 4 mrows x 2 khalf. Partial
//     G written to slot chunk*2+kh; channel sums to slot chunk*2.
// =========================================================================
__global__ __launch_bounds__(256) void k_gram(const float* __restrict__ x) {
    extern __shared__ __align__(16) uint32_t gsm[];
    uint32_t* Xhi = gsm;
    uint32_t* Xlo = gsm + GX_WORDS;

    int b = blockIdx.y, chunk = blockIdx.x;
    int t = threadIdx.x;
    int w = t >> 5, lane = t & 31, g = lane >> 2, tg = lane & 3;
    int mrow = w >> 1, kh = w & 1, m0 = mrow * 16;
    int lch = t >> 2, ltg = t & 3;

    const float* xb = x + (size_t)b * CCH * HWN;
    float csum = 0.f;
    float acc[8][4];
#pragma unroll
    for (int j = 0; j < 8; j++)
#pragma unroll
        for (int r = 0; r < 4; r++) acc[j][r] = 0.f;

    for (int ks = 0; ks < 4; ks++) {
        if (ks) __syncthreads();
        int base = chunk * 1024 + ks * 256;
        const float4* src = reinterpret_cast<const float4*>(xb + (size_t)lch * HWN + base + ltg * 4);
#pragma unroll
        for (int i = 0; i < 16; i++) {
            float4 v = src[i * 4];
            csum += (v.x + v.y) + (v.z + v.w);
            uint32_t h0, l0, h1, l1;
            split2(v.x, v.y, h0, l0);
            split2(v.z, v.w, h1, l1);
            int widx = lch * 132 + ltg * 2 + 8 * i;
            Xhi[widx] = h0; Xhi[widx + 1] = h1;
            Xlo[widx] = l0; Xlo[widx + 1] = l1;
        }
        __syncthreads();

#pragma unroll
        for (int cc = 0; cc < 8; cc++) {
            int pw = (kh * 128 + cc * 16) >> 1;
            int aw = (m0 + g) * 132 + pw + tg;
            uint32_t ahi[4], alo[4];
            ahi[0] = Xhi[aw];            ahi[1] = Xhi[aw + 8 * 132];
            ahi[2] = Xhi[aw + 4];        ahi[3] = Xhi[aw + 8 * 132 + 4];
            alo[0] = Xlo[aw];            alo[1] = Xlo[aw + 8 * 132];
            alo[2] = Xlo[aw + 4];        alo[3] = Xlo[aw + 8 * 132 + 4];
#pragma unroll
            for (int j = 0; j < 8; j++) {
                int bw = (8 * j + g) * 132 + pw + tg;
                uint32_t bh0 = Xhi[bw], bh1 = Xhi[bw + 4];
                uint32_t bl0 = Xlo[bw], bl1 = Xlo[bw + 4];
                mma_bf16(acc[j], ahi, bh0, bh1);
                mma_bf16(acc[j], ahi, bl0, bl1);
                mma_bf16(acc[j], alo, bh0, bh1);
            }
        }
    }

    float* gp = g_part[b][chunk * 2 + kh];
#pragma unroll
    for (int j = 0; j < 8; j++) {
        int col = 8 * j + 2 * tg;
        *reinterpret_cast<float2*>(&gp[(m0 + g) * 64 + col])     = make_float2(acc[j][0], acc[j][1]);
        *reinterpret_cast<float2*>(&gp[(m0 + g + 8) * 64 + col]) = make_float2(acc[j][2], acc[j][3]);
    }
    csum += __shfl_xor_sync(0xffffffffu, csum, 1);
    csum += __shfl_xor_sync(0xffffffffu, csum, 2);
    if (ltg == 0) g_part[b][chunk * 2][4096 + lch] = csum;
}

// =========================================================================
// K2: grid (17, 8). parts 0..15 reduce G over 32 slots; part 16: mean
//     (csum lives in even slots) + routing MLP + tail outputs.
// =========================================================================
__global__ __launch_bounds__(256) void k_route(const float* __restrict__ hidden,
                                               const float* __restrict__ r1w,
                                               const float* __restrict__ r1b,
                                               const float* __restrict__ r3w,
                                               const float* __restrict__ r3b,
                                               float* __restrict__ out, int out_size) {
    int part = blockIdx.x, b = blockIdx.y, t = threadIdx.x;
    if (part < 16) {
        int idx = part * 256 + t;
        float s0 = 0.f, s1 = 0.f, s2 = 0.f, s3 = 0.f;
#pragma unroll
        for (int ch = 0; ch < 32; ch += 4) {
            s0 += g_part[b][ch][idx];
            s1 += g_part[b][ch + 1][idx];
            s2 += g_part[b][ch + 2][idx];
            s3 += g_part[b][ch + 3][idx];
        }
        g_G[b][idx] = (s0 + s1) + (s2 + s3);
        return;
    }
    __shared__ float mean[64];
    __shared__ float hg[16];
    if (t < 64) {
        float s = 0.f;
#pragma unroll
        for (int ch = 0; ch < 16; ch++) s += g_part[b][2 * ch][4096 + t];
        mean[t] = s * (1.0f / 16384.0f);
    }
    __syncthreads();
    if (t < 16) {
        float h = r1b[t];
        for (int c = 0; c < 64; c++) h = fmaf(mean[c], r1w[t * 80 + c], h);
        for (int j = 0; j < 16; j++) h = fmaf(hidden[b * 16 + j], r1w[t * 80 + 64 + j], h);
        float g = 0.5f * h * (1.0f + erff(h * 0.70710678118654752f));
        hg[t] = g;
        int oi = OUTM + b * 16 + t;
        if (oi < out_size) out[oi] = g;
    }
    __syncthreads();
    if (t < 3) {
        float v = r3b[t];
        for (int j = 0; j < 16; j++) v = fmaf(hg[j], r3w[t * 16 + j], v);
        v = fmaxf(v, 0.f);
        g_logit[b][t] = v;
        int oi = OUTM + 128 + b * 3 + t;
        if (oi < out_size) out[oi] = v;
    }
}

// =========================================================================
// K3: grid (3, 8, 4). 4 heads per block: Gram trick, softmax, M1 = A @ Wv.
// =========================================================================
__global__ __launch_bounds__(256) void k_attn(const float* __restrict__ qkvw,
                                              const float* __restrict__ temp) {
    int e = blockIdx.x, b = blockIdx.y, hq = blockIdx.z;
    int r0 = hq * 16;
    __shared__ __align__(16) float Gs[4096];
    __shared__ __align__(16) float tqs[1024];
    __shared__ __align__(16) float tks[1024];
    __shared__ __align__(16) float Wq16[1024];
    __shared__ __align__(16) float Wk16[1024];
    __shared__ float Sraw[64], nq[16], nk[16], A[64];

    int t = threadIdx.x;
    const float* Wq = qkvw + (size_t)e * 192 * 64;
    const float* Wk = Wq + 4096;
    const float* Wv = Wq + 8192;

#pragma unroll
    for (int k = 0; k < 16; k++) Gs[t + 256 * k] = g_G[b][t + 256 * k];
#pragma unroll
    for (int k = 0; k < 4; k++) {
        int idx = t + 256 * k;
        Wq16[idx] = Wq[r0 * 64 + idx];
        Wk16[idx] = Wk[r0 * 64 + idx];
    }
    __syncthreads();

    int ir = t >> 4;
    int c0 = (t & 15) * 4;

    {
        float aq0 = 0.f, aq1 = 0.f, aq2 = 0.f, aq3 = 0.f;
        float ak0 = 0.f, ak1 = 0.f, ak2 = 0.f, ak3 = 0.f;
#pragma unroll 4
        for (int m = 0; m < 64; m++) {
            float wq = Wq16[ir * 64 + m];
            float wk = Wk16[ir * 64 + m];
            float4 g = *reinterpret_cast<const float4*>(&Gs[m * 64 + c0]);
            aq0 = fmaf(wq, g.x, aq0); aq1 = fmaf(wq, g.y, aq1);
            aq2 = fmaf(wq, g.z, aq2); aq3 = fmaf(wq, g.w, aq3);
            ak0 = fmaf(wk, g.x, ak0); ak1 = fmaf(wk, g.y, ak1);
            ak2 = fmaf(wk, g.z, ak2); ak3 = fmaf(wk, g.w, ak3);
        }
        *reinterpret_cast<float4*>(&tqs[ir * 64 + c0]) = make_float4(aq0, aq1, aq2, aq3);
        *reinterpret_cast<float4*>(&tks[ir * 64 + c0]) = make_float4(ak0, ak1, ak2, ak3);
    }
    __syncthreads();

    if (t < 64) {
        int h = t >> 4, a = (t >> 2) & 3, b2 = t & 3;
        int qi = h * 4 + a, kj = h * 4 + b2;
        float s = 0.f;
#pragma unroll 4
        for (int c = 0; c < 64; c += 4) {
            float4 u = *reinterpret_cast<const float4*>(&tqs[qi * 64 + c]);
            float4 w = *reinterpret_cast<const float4*>(&Wk16[kj * 64 + c]);
            s = fmaf(u.x, w.x, s); s = fmaf(u.y, w.y, s);
            s = fmaf(u.z, w.z, s); s = fmaf(u.w, w.w, s);
        }
        Sraw[t] = s;
    } else if (t < 80) {
        int lr = t - 64;
        float s = 0.f;
#pragma unroll 4
        for (int c = 0; c < 64; c += 4) {
            float4 u = *reinterpret_cast<const float4*>(&tqs[lr * 64 + c]);
            float4 w = *reinterpret_cast<const float4*>(&Wq16[lr * 64 + c]);
            s = fmaf(u.x, w.x, s); s = fmaf(u.y, w.y, s);
            s = fmaf(u.z, w.z, s); s = fmaf(u.w, w.w, s);
        }
        nq[lr] = s;
    } else if (t < 96) {
        int lr = t - 80;
        float s = 0.f;
#pragma unroll 4
        for (int c = 0; c < 64; c += 4) {
            float4 u = *reinterpret_cast<const float4*>(&tks[lr * 64 + c]);
            float4 w = *reinterpret_cast<const float4*>(&Wk16[lr * 64 + c]);
            s = fmaf(u.x, w.x, s); s = fmaf(u.y, w.y, s);
            s = fmaf(u.z, w.z, s); s = fmaf(u.w, w.w, s);
        }
        nk[lr] = s;
    }
    __syncthreads();

    if (t < 16) {
        int hl = t >> 2, a = t & 3;
        float qn = fmaxf(sqrtf(nq[t]), 1e-12f);
        float tp = __ldg(&temp[e * 16 + hq * 4 + hl]);
        float v[4];
        float mx = -1e30f;
#pragma unroll
        for (int j = 0; j < 4; j++) {
            float kn = fmaxf(sqrtf(nk[hl * 4 + j]), 1e-12f);
            v[j] = Sraw[hl * 16 + a * 4 + j] / (qn * kn) * tp;
            mx = fmaxf(mx, v[j]);
        }
        float s = 0.f;
#pragma unroll
        for (int j = 0; j < 4; j++) { v[j] = expf(v[j] - mx); s += v[j]; }
        float inv = 1.0f / s;
#pragma unroll
        for (int j = 0; j < 4; j++) A[t * 4 + j] = v[j] * inv;
    }
    __syncthreads();

    {
        int gi = r0 + ir;
        int hb = r0 + (ir >> 2) * 4;
        float a0 = A[ir * 4], a1 = A[ir * 4 + 1], a2 = A[ir * 4 + 2], a3 = A[ir * 4 + 3];
        float4 w0 = *reinterpret_cast<const float4*>(&Wv[(hb + 0) * 64 + c0]);
        float4 w1 = *reinterpret_cast<const float4*>(&Wv[(hb + 1) * 64 + c0]);
        float4 w2 = *reinterpret_cast<const float4*>(&Wv[(hb + 2) * 64 + c0]);
        float4 w3 = *reinterpret_cast<const float4*>(&Wv[(hb + 3) * 64 + c0]);
        float4 o;
        o.x = fmaf(a3, w3.x, fmaf(a2, w2.x, fmaf(a1, w1.x, a0 * w0.x)));
        o.y = fmaf(a3, w3.y, fmaf(a2, w2.y, fmaf(a1, w1.y, a0 * w0.y)));
        o.z = fmaf(a3, w3.z, fmaf(a2, w2.z, fmaf(a1, w1.z, a0 * w0.z)));
        o.w = fmaf(a3, w3.w, fmaf(a2, w2.w, fmaf(a1, w1.w, a0 * w0.w)));
        *reinterpret_cast<float4*>(&g_M1[b][e][gi * 64 + c0]) = o;
    }
}

// =========================================================================
// K4: collapsed conv weights -> bf16 hi/lo planes Bt[n=o][k=c].
//     grid (9, 8, 2): z splits the c dimension (32 cols each). 256 thr.
// =========================================================================
__global__ __launch_bounds__(256) void k_buildR(const float* __restrict__ projw,
                                                const float* __restrict__ dww) {
    int tap = blockIdx.x, b = blockIdx.y, z = blockIdx.z, t = threadIdx.x;
    __shared__ float M1s[64 * 32];
    __shared__ float PsT[64 * 65];
    __shared__ float wds[64];
    int o  = t & 63;
    int cg = (t >> 6) * 8;
    float acc[8];
#pragma unroll
    for (int cc = 0; cc < 8; cc++) acc[cc] = 0.f;

    for (int e = 0; e < 3; e++) {
        __syncthreads();
#pragma unroll
        for (int k = 0; k < 8; k++) {
            int idx = t + 256 * k;                 // 0..2047
            int row = idx >> 5, col = idx & 31;
            M1s[row * 32 + col] = g_M1[b][e][row * 64 + z * 32 + col];
        }
#pragma unroll
        for (int k = 0; k < 16; k++) {
            int idx = t + 256 * k;
            int oo = idx >> 6, mm = idx & 63;
            PsT[mm * 65 + oo] = projw[(size_t)e * 4096 + idx];
        }
        if (t < 64) wds[t] = dww[(size_t)e * 576 + t * 9 + tap];
        __syncthreads();
        float l = g_logit[b][e];
#pragma unroll 4
        for (int m = 0; m < 64; m++) {
            float coef = l * PsT[m * 65 + o] * wds[m];
            const float* mm = &M1s[m * 32 + cg];
#pragma unroll
            for (int cc = 0; cc < 8; cc++) acc[cc] = fmaf(coef, mm[cc], acc[cc]);
        }
    }
    __nv_bfloat16* bh = &g_Bt[b][tap][0][0];
    __nv_bfloat16* bl = &g_Bt[b][tap][1][0];
#pragma unroll
    for (int cc = 0; cc < 8; cc++) {
        int c = z * 32 + cg + cc;
        float v = acc[cc];
        __nv_bfloat16 hi = __float2bfloat16(v);
        __nv_bfloat16 lo = __float2bfloat16(v - __bfloat162float(hi));
        bh[o * 64 + c] = hi;
        bl[o * 64 + c] = lo;
    }
}

// =========================================================================
// K5: warp-MMA conv, pre-split T planes + B register double-buffer.
//     Block = 2 image rows (256 px) x 64 oc; 8 warps, warp tile 32x64.
//     grid (64, 8), 256 threads, dyn smem ~164 KB.
// =========================================================================
__global__ __launch_bounds__(256) void k_convmma(const float* __restrict__ x,
                                                 float* __restrict__ out) {
    extern __shared__ __align__(16) char smem[];
    uint16_t* Thi = reinterpret_cast<uint16_t*>(smem);
    uint16_t* Tlo = reinterpret_cast<uint16_t*>(smem + T_PLANE_B);
    const uint32_t* Twh = reinterpret_cast<const uint32_t*>(smem);
    const uint32_t* Twl = reinterpret_cast<const uint32_t*>(smem + T_PLANE_B);
    uint32_t* Bs = reinterpret_cast<uint32_t*>(smem + BS_OFF);

    const int tid = threadIdx.x;
    const int b = blockIdx.y;
    const int y0 = blockIdx.x * 2;

    const uint32_t* Bg = reinterpret_cast<const uint32_t*>(&g_Bt[b][0][0][0]);
    uint32_t breg[16];
#pragma unroll
    for (int i = 0; i < 16; i++) breg[i] = __ldg(&Bg[tid + i * 256]);   // tap 0

    // stage x rows y0-1..y0+2, px -1..128, 64 ch as bf16 hi/lo planes
    const float* xb = x + (size_t)b * 64 * HWN;
    for (int idx = tid; idx < 4 * 130 * 64; idx += 256) {
        int p = idx % 130;
        int rest = idx / 130;
        int c = rest & 63, ri = rest >> 6;
        int gr = y0 - 1 + ri, gp = p - 1;
        float v = 0.f;
        if ((unsigned)gr < 128u && (unsigned)gp < 128u)
            v = __ldg(&xb[(size_t)c * HWN + gr * 128 + gp]);
        uint32_t u = __float_as_uint(v);
        float lo = v - __uint_as_float(u & 0xffff0000u);
        int hidx = (ri * 130 + p) * 72 + c;
        Thi[hidx] = (uint16_t)(u >> 16);
        Tlo[hidx] = __bfloat16_as_ushort(__float2bfloat16(lo));
    }

    const int w = tid >> 5, lane = tid & 31;
    const int g = lane >> 2, tg = lane & 3;
    const int wrow = w >> 2, wcol = (w & 3) * 32;

    float acc[2][8][4];
#pragma unroll
    for (int s = 0; s < 2; s++)
#pragma unroll
        for (int j = 0; j < 8; j++)
#pragma unroll
            for (int r = 0; r < 4; r++) acc[s][j][r] = 0.f;

    for (int tap = 0; tap < 9; tap++) {
        int dy = tap / 3, dx = tap % 3;
        __syncthreads();   // T staged (tap 0) / prev tap's Bs consumed
        {   // store prefetched B regs -> Bs
            int base = tid;
#pragma unroll
            for (int i = 0; i < 16; i++) {
                int idx = base + i * 256;
                int plane = idx >> 11;
                int rem = idx & 2047;
                int row = rem >> 5, u = rem & 31;
                Bs[plane * BS_WORDS + row * TW_STRIDE + u] = breg[i];
            }
        }
        __syncthreads();
        if (tap < 8) {      // prefetch next tap (hides LDG under MMA)
#pragma unroll
            for (int i = 0; i < 16; i++)
                breg[i] = __ldg(&Bg[(size_t)(tap + 1) * 4096 + tid + i * 256]);
        }

        int ri0 = wrow + dy;
#pragma unroll
        for (int kc = 0; kc < 4; kc++) {
            uint32_t ahi[2][4], alo[2][4];
#pragma unroll
            for (int s = 0; s < 2; s++) {
                int p0 = wcol + s * 16 + g + dx;
                int w0 = (ri0 * 130 + p0) * TW_STRIDE + kc * 8 + tg;
                ahi[s][0] = Twh[w0];       ahi[s][1] = Twh[w0 + 8 * TW_STRIDE];
                ahi[s][2] = Twh[w0 + 4];   ahi[s][3] = Twh[w0 + 8 * TW_STRIDE + 4];
                alo[s][0] = Twl[w0];       alo[s][1] = Twl[w0 + 8 * TW_STRIDE];
                alo[s][2] = Twl[w0 + 4];   alo[s][3] = Twl[w0 + 8 * TW_STRIDE + 4];
            }
#pragma unroll
            for (int j = 0; j < 8; j++) {
                int bw = (j * 8 + g) * TW_STRIDE + kc * 8 + tg;
                uint32_t bh0 = Bs[bw],            bh1 = Bs[bw + 4];
                uint32_t bl0 = Bs[bw + BS_WORDS], bl1 = Bs[bw + BS_WORDS + 4];
#pragma unroll
                for (int s = 0; s < 2; s++) {
                    mma_bf16(acc[s][j], ahi[s], bh0, bh1);
                    mma_bf16(acc[s][j], ahi[s], bl0, bl1);
                    mma_bf16(acc[s][j], alo[s], bh0, bh1);
                }
            }
        }
    }
    __syncthreads();   // all warps done reading T -> reuse as Ds

    float* Ds = reinterpret_cast<float*>(smem);
#pragma unroll
    for (int s = 0; s < 2; s++) {
        int px = wrow * 128 + wcol + s * 16 + g;
#pragma unroll
        for (int j = 0; j < 8; j++) {
            int oc = j * 8 + tg * 2;
            Ds[oc * DS_STRIDE + px]           = acc[s][j][0];
            Ds[(oc + 1) * DS_STRIDE + px]     = acc[s][j][1];
            Ds[oc * DS_STRIDE + px + 8]       = acc[s][j][2];
            Ds[(oc + 1) * DS_STRIDE + px + 8] = acc[s][j][3];
        }
    }
    __syncthreads();

    float* ob = out + (size_t)b * 64 * HWN;
#pragma unroll
    for (int i = 0; i < 16; i++) {
        int idx = tid + i * 256;
        int oc = idx >> 6, f4 = idx & 63;
        int px = f4 * 4;
        float4 v = *reinterpret_cast<const float4*>(&Ds[oc * DS_STRIDE + px]);
        int yy = y0 + (px >> 7), xx = px & 127;
        *reinterpret_cast<float4*>(&ob[((size_t)oc * 128 + yy) * 128 + xx]) = v;
    }
}

// =========================================================================
extern "C" void kernel_launch(void* const* d_in, const int* in_sizes, int n_in,
                              void* d_out, int out_size) {
    const float* x      = (const float*)d_in[0];
    const float* hidden = (const float*)d_in[1];
    const float* qkvw   = (const float*)d_in[2];
    const float* dww    = (const float*)d_in[3];
    const float* projw  = (const float*)d_in[4];
    const float* temp   = (const float*)d_in[5];
    const float* r1w    = (const float*)d_in[6];
    const float* r1b    = (const float*)d_in[7];
    const float* r3w    = (const float*)d_in[8];
    const float* r3b    = (const float*)d_in[9];
    float* out = (float*)d_out;

    cudaFuncSetAttribute(k_gram, cudaFuncAttributeMaxDynamicSharedMemorySize, GSM_TOTAL);
    cudaFuncSetAttribute(k_convmma, cudaFuncAttributeMaxDynamicSharedMemorySize, SM_TOTAL);

    k_gram<<<dim3(16, 8), 256, GSM_TOTAL>>>(x);
    k_route<<<dim3(17, 8), 256>>>(hidden, r1w, r1b, r3w, r3b, out, out_size);
    k_attn<<<dim3(3, 8, 4), 256>>>(qkvw, temp);
    k_buildR<<<dim3(9, 8, 2), 256>>>(projw, dww);
    k_convmma<<<dim3(64, 8), 256, SM_TOTAL>>>(x, out);
}

// round 8
// speedup vs baseline: 5.1865x; 1.3685x over previous
#include <cuda_runtime.h>
#include <cuda_bf16.h>
#include <cuda_fp16.h>
#include <math.h>
#include <stdint.h>

#define BATCH 8
#define CCH   64
#define HH    128
#define WWD   128
#define HWN   (HH*WWD)            // 16384
#define NEXP  3
#define NHEAD 16
#define NHID  16
#define OUTM  (BATCH*CCH*HWN)     // 8388608

// ---------------- scratch (static device globals; no runtime allocs) ----
__device__ float g_part[BATCH][32][4160];     // partial Gram slots (4096) + channel sums (64)
__device__ float g_G[BATCH][4096];            // Gram matrices
__device__ float g_M1[BATCH][NEXP][4096];     // A @ Wv  (per batch, expert)
__device__ float g_logit[BATCH][NEXP];
// collapsed conv weights as fp16 hi/lo planes (scaled by 1024): [b][tap][plane][o*64+c]
__device__ __align__(16) uint16_t g_Bt[BATCH][9][2][4096];

#define B_SCALE   1024.0f
#define B_INV     (1.0f / 1024.0f)

// ---------------- mma.sync helpers (baseline PTX, sm_80+) ---------------
__device__ __forceinline__ void mma_bf16(float* c, const uint32_t* a,
                                         uint32_t b0, uint32_t b1) {
    asm volatile("mma.sync.aligned.m16n8k16.row.col.f32.bf16.bf16.f32 "
        "{%0,%1,%2,%3}, {%4,%5,%6,%7}, {%8,%9}, {%0,%1,%2,%3};"
        : "+f"(c[0]), "+f"(c[1]), "+f"(c[2]), "+f"(c[3])
        : "r"(a[0]), "r"(a[1]), "r"(a[2]), "r"(a[3]), "r"(b0), "r"(b1));
}
__device__ __forceinline__ void mma_f16(float* c, const uint32_t* a,
                                        uint32_t b0, uint32_t b1) {
    asm volatile("mma.sync.aligned.m16n8k16.row.col.f32.f16.f16.f32 "
        "{%0,%1,%2,%3}, {%4,%5,%6,%7}, {%8,%9}, {%0,%1,%2,%3};"
        : "+f"(c[0]), "+f"(c[1]), "+f"(c[2]), "+f"(c[3])
        : "r"(a[0]), "r"(a[1]), "r"(a[2]), "r"(a[3]), "r"(b0), "r"(b1));
}
// split a float2 into packed bf16x2 hi (truncation) and lo (residual, rn)
__device__ __forceinline__ void split2(float fx, float fy, uint32_t& hi, uint32_t& lo) {
    uint32_t u0 = __float_as_uint(fx), u1 = __float_as_uint(fy);
    uint32_t h;
    asm("prmt.b32 %0, %1, %2, 0x7632;" : "=r"(h) : "r"(u0), "r"(u1));
    float l0 = fx - __uint_as_float(u0 & 0xffff0000u);
    float l1 = fy - __uint_as_float(u1 & 0xffff0000u);
    uint32_t l;
    asm("cvt.rn.bf16x2.f32 %0, %1, %2;" : "=r"(l) : "f"(l1), "f"(l0));
    hi = h; lo = l;
}

// ---------------- smem layouts --------------------------------------
// k_gram: 2 planes of [64 ch][132 words] bf16x2
#define GX_WORDS (64 * 132)                    // 8448 words/plane
#define GSM_TOTAL (2 * GX_WORDS * 4)           // 67584 B
// k_convmma: single fp16 T plane (520 plins x 72 halves) + B hi/lo buffer
#define TW_STRIDE 36                           // u32 words per plin
#define T_PLANE_B (520 * 72 * 2)               // 74880 B
#define BS_OFF    T_PLANE_B
#define BS_WORDS  2304                         // words per B plane (64 rows x 36)
#define SM_TOTAL  (BS_OFF + 2 * BS_WORDS * 4)  // 93312
#define DS_STRIDE 268
// k_buildR dynamic smem: 3 experts x (M1 2048 + PsT 4160 + wds 64)
#define BR_SMEM   ((3 * 2048 + 3 * 4160 + 3 * 64) * 4)   // 75264

// =========================================================================
// K1: Gram via warp-MMA (bf16 3-term). grid (16, 8), 256 threads.
// =========================================================================
__global__ __launch_bounds__(256) void k_gram(const float* __restrict__ x) {
    extern __shared__ __align__(16) uint32_t gsm[];
    uint32_t* Xhi = gsm;
    uint32_t* Xlo = gsm + GX_WORDS;

    int b = blockIdx.y, chunk = blockIdx.x;
    int t = threadIdx.x;
    int w = t >> 5, lane = t & 31, g = lane >> 2, tg = lane & 3;
    int mrow = w >> 1, kh = w & 1, m0 = mrow * 16;
    int lch = t >> 2, ltg = t & 3;

    const float* xb = x + (size_t)b * CCH * HWN;
    float csum = 0.f;
    float acc[8][4];
#pragma unroll
    for (int j = 0; j < 8; j++)
#pragma unroll
        for (int r = 0; r < 4; r++) acc[j][r] = 0.f;

    for (int ks = 0; ks < 4; ks++) {
        if (ks) __syncthreads();
        int base = chunk * 1024 + ks * 256;
        const float4* src = reinterpret_cast<const float4*>(xb + (size_t)lch * HWN + base + ltg * 4);
#pragma unroll
        for (int i = 0; i < 16; i++) {
            float4 v = src[i * 4];
            csum += (v.x + v.y) + (v.z + v.w);
            uint32_t h0, l0, h1, l1;
            split2(v.x, v.y, h0, l0);
            split2(v.z, v.w, h1, l1);
            int widx = lch * 132 + ltg * 2 + 8 * i;
            Xhi[widx] = h0; Xhi[widx + 1] = h1;
            Xlo[widx] = l0; Xlo[widx + 1] = l1;
        }
        __syncthreads();

#pragma unroll
        for (int cc = 0; cc < 8; cc++) {
            int pw = (kh * 128 + cc * 16) >> 1;
            int aw = (m0 + g) * 132 + pw + tg;
            uint32_t ahi[4], alo[4];
            ahi[0] = Xhi[aw];            ahi[1] = Xhi[aw + 8 * 132];
            ahi[2] = Xhi[aw + 4];        ahi[3] = Xhi[aw + 8 * 132 + 4];
            alo[0] = Xlo[aw];            alo[1] = Xlo[aw + 8 * 132];
            alo[2] = Xlo[aw + 4];        alo[3] = Xlo[aw + 8 * 132 + 4];
#pragma unroll
            for (int j = 0; j < 8; j++) {
                int bw = (8 * j + g) * 132 + pw + tg;
                uint32_t bh0 = Xhi[bw], bh1 = Xhi[bw + 4];
                uint32_t bl0 = Xlo[bw], bl1 = Xlo[bw + 4];
                mma_bf16(acc[j], ahi, bh0, bh1);
                mma_bf16(acc[j], ahi, bl0, bl1);
                mma_bf16(acc[j], alo, bh0, bh1);
            }
        }
    }

    float* gp = g_part[b][chunk * 2 + kh];
#pragma unroll
    for (int j = 0; j < 8; j++) {
        int col = 8 * j + 2 * tg;
        *reinterpret_cast<float2*>(&gp[(m0 + g) * 64 + col])     = make_float2(acc[j][0], acc[j][1]);
        *reinterpret_cast<float2*>(&gp[(m0 + g + 8) * 64 + col]) = make_float2(acc[j][2], acc[j][3]);
    }
    csum += __shfl_xor_sync(0xffffffffu, csum, 1);
    csum += __shfl_xor_sync(0xffffffffu, csum, 2);
    if (ltg == 0) g_part[b][chunk * 2][4096 + lch] = csum;
}

// =========================================================================
// K2: grid (17, 8). parts 0..15 reduce G over 32 slots; part 16: mean
//     (csum lives in even slots) + routing MLP + tail outputs.
// =========================================================================
__global__ __launch_bounds__(256) void k_route(const float* __restrict__ hidden,
                                               const float* __restrict__ r1w,
                                               const float* __restrict__ r1b,
                                               const float* __restrict__ r3w,
                                               const float* __restrict__ r3b,
                                               float* __restrict__ out, int out_size) {
    int part = blockIdx.x, b = blockIdx.y, t = threadIdx.x;
    if (part < 16) {
        int idx = part * 256 + t;
        float s0 = 0.f, s1 = 0.f, s2 = 0.f, s3 = 0.f;
#pragma unroll
        for (int ch = 0; ch < 32; ch += 4) {
            s0 += g_part[b][ch][idx];
            s1 += g_part[b][ch + 1][idx];
            s2 += g_part[b][ch + 2][idx];
            s3 += g_part[b][ch + 3][idx];
        }
        g_G[b][idx] = (s0 + s1) + (s2 + s3);
        return;
    }
    __shared__ float mean[64];
    __shared__ float hg[16];
    if (t < 64) {
        float s = 0.f;
#pragma unroll
        for (int ch = 0; ch < 16; ch++) s += g_part[b][2 * ch][4096 + t];
        mean[t] = s * (1.0f / 16384.0f);
    }
    __syncthreads();
    if (t < 16) {
        float h = r1b[t];
        for (int c = 0; c < 64; c++) h = fmaf(mean[c], r1w[t * 80 + c], h);
        for (int j = 0; j < 16; j++) h = fmaf(hidden[b * 16 + j], r1w[t * 80 + 64 + j], h);
        float g = 0.5f * h * (1.0f + erff(h * 0.70710678118654752f));
        hg[t] = g;
        int oi = OUTM + b * 16 + t;
        if (oi < out_size) out[oi] = g;
    }
    __syncthreads();
    if (t < 3) {
        float v = r3b[t];
        for (int j = 0; j < 16; j++) v = fmaf(hg[j], r3w[t * 16 + j], v);
        v = fmaxf(v, 0.f);
        g_logit[b][t] = v;
        int oi = OUTM + 128 + b * 3 + t;
        if (oi < out_size) out[oi] = v;
    }
}

// =========================================================================
// K3: grid (3, 8, 4). 4 heads per block: Gram trick, softmax, M1 = A @ Wv.
// =========================================================================
__global__ __launch_bounds__(256) void k_attn(const float* __restrict__ qkvw,
                                              const float* __restrict__ temp) {
    int e = blockIdx.x, b = blockIdx.y, hq = blockIdx.z;
    int r0 = hq * 16;
    __shared__ __align__(16) float Gs[4096];
    __shared__ __align__(16) float tqs[1024];
    __shared__ __align__(16) float tks[1024];
    __shared__ __align__(16) float Wq16[1024];
    __shared__ __align__(16) float Wk16[1024];
    __shared__ float Sraw[64], nq[16], nk[16], A[64];

    int t = threadIdx.x;
    const float* Wq = qkvw + (size_t)e * 192 * 64;
    const float* Wk = Wq + 4096;
    const float* Wv = Wq + 8192;

#pragma unroll
    for (int k = 0; k < 16; k++) Gs[t + 256 * k] = g_G[b][t + 256 * k];
#pragma unroll
    for (int k = 0; k < 4; k++) {
        int idx = t + 256 * k;
        Wq16[idx] = Wq[r0 * 64 + idx];
        Wk16[idx] = Wk[r0 * 64 + idx];
    }
    __syncthreads();

    int ir = t >> 4;
    int c0 = (t & 15) * 4;

    {
        float aq0 = 0.f, aq1 = 0.f, aq2 = 0.f, aq3 = 0.f;
        float ak0 = 0.f, ak1 = 0.f, ak2 = 0.f, ak3 = 0.f;
#pragma unroll 4
        for (int m = 0; m < 64; m++) {
            float wq = Wq16[ir * 64 + m];
            float wk = Wk16[ir * 64 + m];
            float4 g = *reinterpret_cast<const float4*>(&Gs[m * 64 + c0]);
            aq0 = fmaf(wq, g.x, aq0); aq1 = fmaf(wq, g.y, aq1);
            aq2 = fmaf(wq, g.z, aq2); aq3 = fmaf(wq, g.w, aq3);
            ak0 = fmaf(wk, g.x, ak0); ak1 = fmaf(wk, g.y, ak1);
            ak2 = fmaf(wk, g.z, ak2); ak3 = fmaf(wk, g.w, ak3);
        }
        *reinterpret_cast<float4*>(&tqs[ir * 64 + c0]) = make_float4(aq0, aq1, aq2, aq3);
        *reinterpret_cast<float4*>(&tks[ir * 64 + c0]) = make_float4(ak0, ak1, ak2, ak3);
    }
    __syncthreads();

    if (t < 64) {
        int h = t >> 4, a = (t >> 2) & 3, b2 = t & 3;
        int qi = h * 4 + a, kj = h * 4 + b2;
        float s = 0.f;
#pragma unroll 4
        for (int c = 0; c < 64; c += 4) {
            float4 u = *reinterpret_cast<const float4*>(&tqs[qi * 64 + c]);
            float4 w = *reinterpret_cast<const float4*>(&Wk16[kj * 64 + c]);
            s = fmaf(u.x, w.x, s); s = fmaf(u.y, w.y, s);
            s = fmaf(u.z, w.z, s); s = fmaf(u.w, w.w, s);
        }
        Sraw[t] = s;
    } else if (t < 80) {
        int lr = t - 64;
        float s = 0.f;
#pragma unroll 4
        for (int c = 0; c < 64; c += 4) {
            float4 u = *reinterpret_cast<const float4*>(&tqs[lr * 64 + c]);
            float4 w = *reinterpret_cast<const float4*>(&Wq16[lr * 64 + c]);
            s = fmaf(u.x, w.x, s); s = fmaf(u.y, w.y, s);
            s = fmaf(u.z, w.z, s); s = fmaf(u.w, w.w, s);
        }
        nq[lr] = s;
    } else if (t < 96) {
        int lr = t - 80;
        float s = 0.f;
#pragma unroll 4
        for (int c = 0; c < 64; c += 4) {
            float4 u = *reinterpret_cast<const float4*>(&tks[lr * 64 + c]);
            float4 w = *reinterpret_cast<const float4*>(&Wk16[lr * 64 + c]);
            s = fmaf(u.x, w.x, s); s = fmaf(u.y, w.y, s);
            s = fmaf(u.z, w.z, s); s = fmaf(u.w, w.w, s);
        }
        nk[lr] = s;
    }
    __syncthreads();

    if (t < 16) {
        int hl = t >> 2, a = t & 3;
        float qn = fmaxf(sqrtf(nq[t]), 1e-12f);
        float tp = __ldg(&temp[e * 16 + hq * 4 + hl]);
        float v[4];
        float mx = -1e30f;
#pragma unroll
        for (int j = 0; j < 4; j++) {
            float kn = fmaxf(sqrtf(nk[hl * 4 + j]), 1e-12f);
            v[j] = Sraw[hl * 16 + a * 4 + j] / (qn * kn) * tp;
            mx = fmaxf(mx, v[j]);
        }
        float s = 0.f;
#pragma unroll
        for (int j = 0; j < 4; j++) { v[j] = expf(v[j] - mx); s += v[j]; }
        float inv = 1.0f / s;
#pragma unroll
        for (int j = 0; j < 4; j++) A[t * 4 + j] = v[j] * inv;
    }
    __syncthreads();

    {
        int gi = r0 + ir;
        int hb = r0 + (ir >> 2) * 4;
        float a0 = A[ir * 4], a1 = A[ir * 4 + 1], a2 = A[ir * 4 + 2], a3 = A[ir * 4 + 3];
        float4 w0 = *reinterpret_cast<const float4*>(&Wv[(hb + 0) * 64 + c0]);
        float4 w1 = *reinterpret_cast<const float4*>(&Wv[(hb + 1) * 64 + c0]);
        float4 w2 = *reinterpret_cast<const float4*>(&Wv[(hb + 2) * 64 + c0]);
        float4 w3 = *reinterpret_cast<const float4*>(&Wv[(hb + 3) * 64 + c0]);
        float4 o;
        o.x = fmaf(a3, w3.x, fmaf(a2, w2.x, fmaf(a1, w1.x, a0 * w0.x)));
        o.y = fmaf(a3, w3.y, fmaf(a2, w2.y, fmaf(a1, w1.y, a0 * w0.y)));
        o.z = fmaf(a3, w3.z, fmaf(a2, w2.z, fmaf(a1, w1.z, a0 * w0.z)));
        o.w = fmaf(a3, w3.w, fmaf(a2, w2.w, fmaf(a1, w1.w, a0 * w0.w)));
        *reinterpret_cast<float4*>(&g_M1[b][e][gi * 64 + c0]) = o;
    }
}

// =========================================================================
// K4: collapsed conv weights -> fp16 hi/lo planes (x B_SCALE).
//     grid (9, 8, 2), 256 thr. ALL expert operands prefetched to smem in
//     one LDG batch (single latency exposure), then compute sync-free.
// =========================================================================
__global__ __launch_bounds__(256) void k_buildR(const float* __restrict__ projw,
                                                const float* __restrict__ dww) {
    extern __shared__ float bsm[];
    float* M1s = bsm;                         // [e][64][32]
    float* PsT = bsm + 3 * 2048;              // [e][m*65+o]
    float* wds = bsm + 3 * 2048 + 3 * 4160;   // [e][64]
    int tap = blockIdx.x, b = blockIdx.y, z = blockIdx.z, t = threadIdx.x;
    int o  = t & 63;
    int cg = (t >> 6) * 8;
    float lg[3];

#pragma unroll
    for (int e = 0; e < 3; e++) {
#pragma unroll
        for (int k = 0; k < 8; k++) {
            int idx = t + 256 * k;
            int row = idx >> 5, col = idx & 31;
            M1s[e * 2048 + row * 32 + col] = g_M1[b][e][row * 64 + z * 32 + col];
        }
#pragma unroll
        for (int k = 0; k < 16; k++) {
            int idx = t + 256 * k;
            int oo = idx >> 6, mm = idx & 63;
            PsT[e * 4160 + mm * 65 + oo] = projw[(size_t)e * 4096 + idx];
        }
        if (t < 64) wds[e * 64 + t] = dww[(size_t)e * 576 + t * 9 + tap];
        lg[e] = g_logit[b][e];
    }
    __syncthreads();

    float acc[8];
#pragma unroll
    for (int cc = 0; cc < 8; cc++) acc[cc] = 0.f;

#pragma unroll
    for (int e = 0; e < 3; e++) {
        float l = lg[e];
        const float* P  = &PsT[e * 4160];
        const float* wd = &wds[e * 64];
        const float* M  = &M1s[e * 2048];
#pragma unroll 4
        for (int m = 0; m < 64; m++) {
            float coef = l * P[m * 65 + o] * wd[m];
            const float* mm = &M[m * 32 + cg];
#pragma unroll
            for (int cc = 0; cc < 8; cc++) acc[cc] = fmaf(coef, mm[cc], acc[cc]);
        }
    }
    uint16_t* bh = &g_Bt[b][tap][0][0];
    uint16_t* bl = &g_Bt[b][tap][1][0];
#pragma unroll
    for (int cc = 0; cc < 8; cc++) {
        int c = z * 32 + cg + cc;
        float vs = acc[cc] * B_SCALE;
        __half h = __float2half_rn(vs);
        float r = vs - __half2float(h);
        bh[o * 64 + c] = __half_as_ushort(h);
        bl[o * 64 + c] = __half_as_ushort(__float2half_rn(r));
    }
}

// =========================================================================
// K5: warp-MMA conv — fp16 2-term (A single fp16, B hi+lo fp16, scaled).
//     Block = 2 image rows (256 px) x 64 oc; 8 warps, warp tile 32x64.
//     grid (64, 8), 256 threads, dyn smem ~91 KB -> 2 blocks/SM.
// =========================================================================
__global__ __launch_bounds__(256, 2) void k_convmma(const float* __restrict__ x,
                                                    float* __restrict__ out) {
    extern __shared__ __align__(16) char smem[];
    uint16_t* Th = reinterpret_cast<uint16_t*>(smem);
    const uint32_t* Twh = reinterpret_cast<const uint32_t*>(smem);
    uint32_t* Bs = reinterpret_cast<uint32_t*>(smem + BS_OFF);

    const int tid = threadIdx.x;
    const int b = blockIdx.y;
    const int y0 = blockIdx.x * 2;

    const uint32_t* Bg = reinterpret_cast<const uint32_t*>(&g_Bt[b][0][0][0]);
    uint32_t breg[16];
#pragma unroll
    for (int i = 0; i < 16; i++) breg[i] = __ldg(&Bg[tid + i * 256]);   // tap 0

    // stage x rows y0-1..y0+2, px -1..128, 64 ch as a single fp16 plane
    const float* xb = x + (size_t)b * 64 * HWN;
    for (int idx = tid; idx < 4 * 130 * 64; idx += 256) {
        int p = idx % 130;
        int rest = idx / 130;
        int c = rest & 63, ri = rest >> 6;
        int gr = y0 - 1 + ri, gp = p - 1;
        float v = 0.f;
        if ((unsigned)gr < 128u && (unsigned)gp < 128u)
            v = __ldg(&xb[(size_t)c * HWN + gr * 128 + gp]);
        Th[(ri * 130 + p) * 72 + c] = __half_as_ushort(__float2half_rn(v));
    }

    const int w = tid >> 5, lane = tid & 31;
    const int g = lane >> 2, tg = lane & 3;
    const int wrow = w >> 2, wcol = (w & 3) * 32;

    float acc[2][8][4];
#pragma unroll
    for (int s = 0; s < 2; s++)
#pragma unroll
        for (int j = 0; j < 8; j++)
#pragma unroll
            for (int r = 0; r < 4; r++) acc[s][j][r] = 0.f;

    for (int tap = 0; tap < 9; tap++) {
        int dy = tap / 3, dx = tap % 3;
        __syncthreads();   // T staged (tap 0) / prev tap's Bs consumed
        {   // store prefetched B regs -> Bs
#pragma unroll
            for (int i = 0; i < 16; i++) {
                int idx = tid + i * 256;
                int plane = idx >> 11;
                int rem = idx & 2047;
                int row = rem >> 5, u = rem & 31;
                Bs[plane * BS_WORDS + row * TW_STRIDE + u] = breg[i];
            }
        }
        __syncthreads();
        if (tap < 8) {      // prefetch next tap (hides LDG under MMA)
#pragma unroll
            for (int i = 0; i < 16; i++)
                breg[i] = __ldg(&Bg[(size_t)(tap + 1) * 4096 + tid + i * 256]);
        }

        int ri0 = wrow + dy;
#pragma unroll
        for (int kc = 0; kc < 4; kc++) {
            uint32_t ahi[2][4];
#pragma unroll
            for (int s = 0; s < 2; s++) {
                int p0 = wcol + s * 16 + g + dx;
                int w0 = (ri0 * 130 + p0) * TW_STRIDE + kc * 8 + tg;
                ahi[s][0] = Twh[w0];       ahi[s][1] = Twh[w0 + 8 * TW_STRIDE];
                ahi[s][2] = Twh[w0 + 4];   ahi[s][3] = Twh[w0 + 8 * TW_STRIDE + 4];
            }
#pragma unroll
            for (int j = 0; j < 8; j++) {
                int bw = (j * 8 + g) * TW_STRIDE + kc * 8 + tg;
                uint32_t bh0 = Bs[bw],            bh1 = Bs[bw + 4];
                uint32_t bl0 = Bs[bw + BS_WORDS], bl1 = Bs[bw + BS_WORDS + 4];
#pragma unroll
                for (int s = 0; s < 2; s++) {
                    mma_f16(acc[s][j], ahi[s], bh0, bh1);
                    mma_f16(acc[s][j], ahi[s], bl0, bl1);
                }
            }
        }
    }
    __syncthreads();   // all warps done reading T -> reuse as Ds

    // scatter accs (undoing the B_SCALE) to Ds[oc][px]
    float* Ds = reinterpret_cast<float*>(smem);
#pragma unroll
    for (int s = 0; s < 2; s++) {
        int px = wrow * 128 + wcol + s * 16 + g;
#pragma unroll
        for (int j = 0; j < 8; j++) {
            int oc = j * 8 + tg * 2;
            Ds[oc * DS_STRIDE + px]           = acc[s][j][0] * B_INV;
            Ds[(oc + 1) * DS_STRIDE + px]     = acc[s][j][1] * B_INV;
            Ds[oc * DS_STRIDE + px + 8]       = acc[s][j][2] * B_INV;
            Ds[(oc + 1) * DS_STRIDE + px + 8] = acc[s][j][3] * B_INV;
        }
    }
    __syncthreads();

    float* ob = out + (size_t)b * 64 * HWN;
#pragma unroll
    for (int i = 0; i < 16; i++) {
        int idx = tid + i * 256;
        int oc = idx >> 6, f4 = idx & 63;
        int px = f4 * 4;
        float4 v = *reinterpret_cast<const float4*>(&Ds[oc * DS_STRIDE + px]);
        int yy = y0 + (px >> 7), xx = px & 127;
        *reinterpret_cast<float4*>(&ob[((size_t)oc * 128 + yy) * 128 + xx]) = v;
    }
}

// =========================================================================
extern "C" void kernel_launch(void* const* d_in, const int* in_sizes, int n_in,
                              void* d_out, int out_size) {
    const float* x      = (const float*)d_in[0];
    const float* hidden = (const float*)d_in[1];
    const float* qkvw   = (const float*)d_in[2];
    const float* dww    = (const float*)d_in[3];
    const float* projw  = (const float*)d_in[4];
    const float* temp   = (const float*)d_in[5];
    const float* r1w    = (const float*)d_in[6];
    const float* r1b    = (const float*)d_in[7];
    const float* r3w    = (const float*)d_in[8];
    const float* r3b    = (const float*)d_in[9];
    float* out = (float*)d_out;

    cudaFuncSetAttribute(k_gram, cudaFuncAttributeMaxDynamicSharedMemorySize, GSM_TOTAL);
    cudaFuncSetAttribute(k_buildR, cudaFuncAttributeMaxDynamicSharedMemorySize, BR_SMEM);
    cudaFuncSetAttribute(k_convmma, cudaFuncAttributeMaxDynamicSharedMemorySize, SM_TOTAL);

    k_gram<<<dim3(16, 8), 256, GSM_TOTAL>>>(x);
    k_route<<<dim3(17, 8), 256>>>(hidden, r1w, r1b, r3w, r3b, out, out_size);
    k_attn<<<dim3(3, 8, 4), 256>>>(qkvw, temp);
    k_buildR<<<dim3(9, 8, 2), 256, BR_SMEM>>>(projw, dww);
    k_convmma<<<dim3(64, 8), 256, SM_TOTAL>>>(x, out);
}

// round 9
// speedup vs baseline: 6.0551x; 1.1675x over previous
#include <cuda_runtime.h>
#include <cuda_bf16.h>
#include <cuda_fp16.h>
#include <math.h>
#include <stdint.h>

#define BATCH 8
#define CCH   64
#define HH    128
#define WWD   128
#define HWN   (HH*WWD)            // 16384
#define NEXP  3
#define NHEAD 16
#define NHID  16
#define OUTM  (BATCH*CCH*HWN)     // 8388608

// ---------------- scratch (static device globals; no runtime allocs) ----
__device__ float g_part[BATCH][32][4160];     // partial Gram slots (4096) + channel sums (64)
__device__ float g_G[BATCH][4096];            // Gram matrices
__device__ float g_M1[BATCH][NEXP][4096];     // A @ Wv  (per batch, expert)
__device__ float g_logit[BATCH][NEXP];
// collapsed conv weights, single fp16 plane (scaled by 1024): [b][tap][o*64+c]
__device__ __align__(16) uint16_t g_Bt[BATCH][9][4096];

#define B_SCALE   1024.0f
#define B_INV     (1.0f / 1024.0f)

// ---------------- mma.sync helpers (baseline PTX, sm_80+) ---------------
__device__ __forceinline__ void mma_bf16(float* c, const uint32_t* a,
                                         uint32_t b0, uint32_t b1) {
    asm volatile("mma.sync.aligned.m16n8k16.row.col.f32.bf16.bf16.f32 "
        "{%0,%1,%2,%3}, {%4,%5,%6,%7}, {%8,%9}, {%0,%1,%2,%3};"
        : "+f"(c[0]), "+f"(c[1]), "+f"(c[2]), "+f"(c[3])
        : "r"(a[0]), "r"(a[1]), "r"(a[2]), "r"(a[3]), "r"(b0), "r"(b1));
}
__device__ __forceinline__ void mma_f16(float* c, const uint32_t* a,
                                        uint32_t b0, uint32_t b1) {
    asm volatile("mma.sync.aligned.m16n8k16.row.col.f32.f16.f16.f32 "
        "{%0,%1,%2,%3}, {%4,%5,%6,%7}, {%8,%9}, {%0,%1,%2,%3};"
        : "+f"(c[0]), "+f"(c[1]), "+f"(c[2]), "+f"(c[3])
        : "r"(a[0]), "r"(a[1]), "r"(a[2]), "r"(a[3]), "r"(b0), "r"(b1));
}
// split a float2 into packed bf16x2 hi (truncation) and lo (residual, rn)
__device__ __forceinline__ void split2(float fx, float fy, uint32_t& hi, uint32_t& lo) {
    uint32_t u0 = __float_as_uint(fx), u1 = __float_as_uint(fy);
    uint32_t h;
    asm("prmt.b32 %0, %1, %2, 0x7632;" : "=r"(h) : "r"(u0), "r"(u1));
    float l0 = fx - __uint_as_float(u0 & 0xffff0000u);
    float l1 = fy - __uint_as_float(u1 & 0xffff0000u);
    uint32_t l;
    asm("cvt.rn.bf16x2.f32 %0, %1, %2;" : "=r"(l) : "f"(l1), "f"(l0));
    hi = h; lo = l;
}

// ---------------- smem layouts --------------------------------------
// k_gram: 2 planes of [64 ch][132 words] bf16x2
#define GX_WORDS (64 * 132)                    // 8448 words/plane
#define GSM_TOTAL (2 * GX_WORDS * 4)           // 67584 B
// k_convmma: single fp16 T plane (520 plins x 72 halves) + single B plane
#define TW_STRIDE 36                           // u32 words per plin
#define T_PLANE_B (520 * 72 * 2)               // 74880 B
#define BS_OFF    T_PLANE_B
#define BS_WORDS  2304                         // words per B plane (64 rows x 36)
#define SM_TOTAL  (BS_OFF + BS_WORDS * 4)      // 84096
#define DS_STRIDE 268
// k_buildR dynamic smem: 3 experts x (M1 1024 + PsT 4160 + wds 64)
#define BR_SMEM   ((3 * 1024 + 3 * 4160 + 3 * 64) * 4)   // 62976

// =========================================================================
// K1: Gram via warp-MMA (bf16 3-term). grid (16, 8), 256 threads.
// =========================================================================
__global__ __launch_bounds__(256) void k_gram(const float* __restrict__ x) {
    extern __shared__ __align__(16) uint32_t gsm[];
    uint32_t* Xhi = gsm;
    uint32_t* Xlo = gsm + GX_WORDS;

    int b = blockIdx.y, chunk = blockIdx.x;
    int t = threadIdx.x;
    int w = t >> 5, lane = t & 31, g = lane >> 2, tg = lane & 3;
    int mrow = w >> 1, kh = w & 1, m0 = mrow * 16;
    int lch = t >> 2, ltg = t & 3;

    const float* xb = x + (size_t)b * CCH * HWN;
    float csum = 0.f;
    float acc[8][4];
#pragma unroll
    for (int j = 0; j < 8; j++)
#pragma unroll
        for (int r = 0; r < 4; r++) acc[j][r] = 0.f;

    for (int ks = 0; ks < 4; ks++) {
        if (ks) __syncthreads();
        int base = chunk * 1024 + ks * 256;
        const float4* src = reinterpret_cast<const float4*>(xb + (size_t)lch * HWN + base + ltg * 4);
#pragma unroll
        for (int i = 0; i < 16; i++) {
            float4 v = src[i * 4];
            csum += (v.x + v.y) + (v.z + v.w);
            uint32_t h0, l0, h1, l1;
            split2(v.x, v.y, h0, l0);
            split2(v.z, v.w, h1, l1);
            int widx = lch * 132 + ltg * 2 + 8 * i;
            Xhi[widx] = h0; Xhi[widx + 1] = h1;
            Xlo[widx] = l0; Xlo[widx + 1] = l1;
        }
        __syncthreads();

#pragma unroll
        for (int cc = 0; cc < 8; cc++) {
            int pw = (kh * 128 + cc * 16) >> 1;
            int aw = (m0 + g) * 132 + pw + tg;
            uint32_t ahi[4], alo[4];
            ahi[0] = Xhi[aw];            ahi[1] = Xhi[aw + 8 * 132];
            ahi[2] = Xhi[aw + 4];        ahi[3] = Xhi[aw + 8 * 132 + 4];
            alo[0] = Xlo[aw];            alo[1] = Xlo[aw + 8 * 132];
            alo[2] = Xlo[aw + 4];        alo[3] = Xlo[aw + 8 * 132 + 4];
#pragma unroll
            for (int j = 0; j < 8; j++) {
                int bw = (8 * j + g) * 132 + pw + tg;
                uint32_t bh0 = Xhi[bw], bh1 = Xhi[bw + 4];
                uint32_t bl0 = Xlo[bw], bl1 = Xlo[bw + 4];
                mma_bf16(acc[j], ahi, bh0, bh1);
                mma_bf16(acc[j], ahi, bl0, bl1);
                mma_bf16(acc[j], alo, bh0, bh1);
            }
        }
    }

    float* gp = g_part[b][chunk * 2 + kh];
#pragma unroll
    for (int j = 0; j < 8; j++) {
        int col = 8 * j + 2 * tg;
        *reinterpret_cast<float2*>(&gp[(m0 + g) * 64 + col])     = make_float2(acc[j][0], acc[j][1]);
        *reinterpret_cast<float2*>(&gp[(m0 + g + 8) * 64 + col]) = make_float2(acc[j][2], acc[j][3]);
    }
    csum += __shfl_xor_sync(0xffffffffu, csum, 1);
    csum += __shfl_xor_sync(0xffffffffu, csum, 2);
    if (ltg == 0) g_part[b][chunk * 2][4096 + lch] = csum;
}

// =========================================================================
// K2: grid (17, 8). parts 0..15 reduce G over 32 slots; part 16: mean
//     (csum lives in even slots) + routing MLP + tail outputs.
// =========================================================================
__global__ __launch_bounds__(256) void k_route(const float* __restrict__ hidden,
                                               const float* __restrict__ r1w,
                                               const float* __restrict__ r1b,
                                               const float* __restrict__ r3w,
                                               const float* __restrict__ r3b,
                                               float* __restrict__ out, int out_size) {
    int part = blockIdx.x, b = blockIdx.y, t = threadIdx.x;
    if (part < 16) {
        int idx = part * 256 + t;
        float s0 = 0.f, s1 = 0.f, s2 = 0.f, s3 = 0.f;
#pragma unroll
        for (int ch = 0; ch < 32; ch += 4) {
            s0 += g_part[b][ch][idx];
            s1 += g_part[b][ch + 1][idx];
            s2 += g_part[b][ch + 2][idx];
            s3 += g_part[b][ch + 3][idx];
        }
        g_G[b][idx] = (s0 + s1) + (s2 + s3);
        return;
    }
    __shared__ float mean[64];
    __shared__ float hg[16];
    if (t < 64) {
        float s = 0.f;
#pragma unroll
        for (int ch = 0; ch < 16; ch++) s += g_part[b][2 * ch][4096 + t];
        mean[t] = s * (1.0f / 16384.0f);
    }
    __syncthreads();
    if (t < 16) {
        float h = r1b[t];
        for (int c = 0; c < 64; c++) h = fmaf(mean[c], r1w[t * 80 + c], h);
        for (int j = 0; j < 16; j++) h = fmaf(hidden[b * 16 + j], r1w[t * 80 + 64 + j], h);
        float g = 0.5f * h * (1.0f + erff(h * 0.70710678118654752f));
        hg[t] = g;
        int oi = OUTM + b * 16 + t;
        if (oi < out_size) out[oi] = g;
    }
    __syncthreads();
    if (t < 3) {
        float v = r3b[t];
        for (int j = 0; j < 16; j++) v = fmaf(hg[j], r3w[t * 16 + j], v);
        v = fmaxf(v, 0.f);
        g_logit[b][t] = v;
        int oi = OUTM + 128 + b * 3 + t;
        if (oi < out_size) out[oi] = v;
    }
}

// =========================================================================
// K3: grid (3, 8, 4). 4 heads per block: Gram trick, softmax, M1 = A @ Wv.
// =========================================================================
__global__ __launch_bounds__(256) void k_attn(const float* __restrict__ qkvw,
                                              const float* __restrict__ temp) {
    int e = blockIdx.x, b = blockIdx.y, hq = blockIdx.z;
    int r0 = hq * 16;
    __shared__ __align__(16) float Gs[4096];
    __shared__ __align__(16) float tqs[1024];
    __shared__ __align__(16) float tks[1024];
    __shared__ __align__(16) float Wq16[1024];
    __shared__ __align__(16) float Wk16[1024];
    __shared__ float Sraw[64], nq[16], nk[16], A[64];

    int t = threadIdx.x;
    const float* Wq = qkvw + (size_t)e * 192 * 64;
    const float* Wk = Wq + 4096;
    const float* Wv = Wq + 8192;

#pragma unroll
    for (int k = 0; k < 16; k++) Gs[t + 256 * k] = g_G[b][t + 256 * k];
#pragma unroll
    for (int k = 0; k < 4; k++) {
        int idx = t + 256 * k;
        Wq16[idx] = Wq[r0 * 64 + idx];
        Wk16[idx] = Wk[r0 * 64 + idx];
    }
    __syncthreads();

    int ir = t >> 4;
    int c0 = (t & 15) * 4;

    {
        float aq0 = 0.f, aq1 = 0.f, aq2 = 0.f, aq3 = 0.f;
        float ak0 = 0.f, ak1 = 0.f, ak2 = 0.f, ak3 = 0.f;
#pragma unroll 4
        for (int m = 0; m < 64; m++) {
            float wq = Wq16[ir * 64 + m];
            float wk = Wk16[ir * 64 + m];
            float4 g = *reinterpret_cast<const float4*>(&Gs[m * 64 + c0]);
            aq0 = fmaf(wq, g.x, aq0); aq1 = fmaf(wq, g.y, aq1);
            aq2 = fmaf(wq, g.z, aq2); aq3 = fmaf(wq, g.w, aq3);
            ak0 = fmaf(wk, g.x, ak0); ak1 = fmaf(wk, g.y, ak1);
            ak2 = fmaf(wk, g.z, ak2); ak3 = fmaf(wk, g.w, ak3);
        }
        *reinterpret_cast<float4*>(&tqs[ir * 64 + c0]) = make_float4(aq0, aq1, aq2, aq3);
        *reinterpret_cast<float4*>(&tks[ir * 64 + c0]) = make_float4(ak0, ak1, ak2, ak3);
    }
    __syncthreads();

    if (t < 64) {
        int h = t >> 4, a = (t >> 2) & 3, b2 = t & 3;
        int qi = h * 4 + a, kj = h * 4 + b2;
        float s = 0.f;
#pragma unroll 4
        for (int c = 0; c < 64; c += 4) {
            float4 u = *reinterpret_cast<const float4*>(&tqs[qi * 64 + c]);
            float4 w = *reinterpret_cast<const float4*>(&Wk16[kj * 64 + c]);
            s = fmaf(u.x, w.x, s); s = fmaf(u.y, w.y, s);
            s = fmaf(u.z, w.z, s); s = fmaf(u.w, w.w, s);
        }
        Sraw[t] = s;
    } else if (t < 80) {
        int lr = t - 64;
        float s = 0.f;
#pragma unroll 4
        for (int c = 0; c < 64; c += 4) {
            float4 u = *reinterpret_cast<const float4*>(&tqs[lr * 64 + c]);
            float4 w = *reinterpret_cast<const float4*>(&Wq16[lr * 64 + c]);
            s = fmaf(u.x, w.x, s); s = fmaf(u.y, w.y, s);
            s = fmaf(u.z, w.z, s); s = fmaf(u.w, w.w, s);
        }
        nq[lr] = s;
    } else if (t < 96) {
        int lr = t - 80;
        float s = 0.f;
#pragma unroll 4
        for (int c = 0; c < 64; c += 4) {
            float4 u = *reinterpret_cast<const float4*>(&tks[lr * 64 + c]);
            float4 w = *reinterpret_cast<const float4*>(&Wk16[lr * 64 + c]);
            s = fmaf(u.x, w.x, s); s = fmaf(u.y, w.y, s);
            s = fmaf(u.z, w.z, s); s = fmaf(u.w, w.w, s);
        }
        nk[lr] = s;
    }
    __syncthreads();

    if (t < 16) {
        int hl = t >> 2, a = t & 3;
        float qn = fmaxf(sqrtf(nq[t]), 1e-12f);
        float tp = __ldg(&temp[e * 16 + hq * 4 + hl]);
        float v[4];
        float mx = -1e30f;
#pragma unroll
        for (int j = 0; j < 4; j++) {
            float kn = fmaxf(sqrtf(nk[hl * 4 + j]), 1e-12f);
            v[j] = Sraw[hl * 16 + a * 4 + j] / (qn * kn) * tp;
            mx = fmaxf(mx, v[j]);
        }
        float s = 0.f;
#pragma unroll
        for (int j = 0; j < 4; j++) { v[j] = expf(v[j] - mx); s += v[j]; }
        float inv = 1.0f / s;
#pragma unroll
        for (int j = 0; j < 4; j++) A[t * 4 + j] = v[j] * inv;
    }
    __syncthreads();

    {
        int gi = r0 + ir;
        int hb = r0 + (ir >> 2) * 4;
        float a0 = A[ir * 4], a1 = A[ir * 4 + 1], a2 = A[ir * 4 + 2], a3 = A[ir * 4 + 3];
        float4 w0 = *reinterpret_cast<const float4*>(&Wv[(hb + 0) * 64 + c0]);
        float4 w1 = *reinterpret_cast<const float4*>(&Wv[(hb + 1) * 64 + c0]);
        float4 w2 = *reinterpret_cast<const float4*>(&Wv[(hb + 2) * 64 + c0]);
        float4 w3 = *reinterpret_cast<const float4*>(&Wv[(hb + 3) * 64 + c0]);
        float4 o;
        o.x = fmaf(a3, w3.x, fmaf(a2, w2.x, fmaf(a1, w1.x, a0 * w0.x)));
        o.y = fmaf(a3, w3.y, fmaf(a2, w2.y, fmaf(a1, w1.y, a0 * w0.y)));
        o.z = fmaf(a3, w3.z, fmaf(a2, w2.z, fmaf(a1, w1.z, a0 * w0.z)));
        o.w = fmaf(a3, w3.w, fmaf(a2, w2.w, fmaf(a1, w1.w, a0 * w0.w)));
        *reinterpret_cast<float4*>(&g_M1[b][e][gi * 64 + c0]) = o;
    }
}

// =========================================================================
// K4: collapsed conv weights -> single fp16 plane (x B_SCALE).
//     grid (9, 8, 4), 256 thr; z = 16-col slice. All expert operands
//     prefetched to smem in one LDG volley, then compute sync-free.
// =========================================================================
__global__ __launch_bounds__(256) void k_buildR(const float* __restrict__ projw,
                                                const float* __restrict__ dww) {
    extern __shared__ float bsm[];
    float* M1s = bsm;                         // [e][64][16]
    float* PsT = bsm + 3 * 1024;              // [e][m*65+o]
    float* wds = bsm + 3 * 1024 + 3 * 4160;   // [e][64]
    int tap = blockIdx.x, b = blockIdx.y, z = blockIdx.z, t = threadIdx.x;
    int o  = t & 63;
    int cg = (t >> 6) * 4;
    float lg[3];

#pragma unroll
    for (int e = 0; e < 3; e++) {
#pragma unroll
        for (int k = 0; k < 4; k++) {
            int idx = t + 256 * k;                 // 0..1023
            int row = idx >> 4, col = idx & 15;
            M1s[e * 1024 + row * 16 + col] = g_M1[b][e][row * 64 + z * 16 + col];
        }
#pragma unroll
        for (int k = 0; k < 16; k++) {
            int idx = t + 256 * k;
            int oo = idx >> 6, mm = idx & 63;
            PsT[e * 4160 + mm * 65 + oo] = projw[(size_t)e * 4096 + idx];
        }
        if (t < 64) wds[e * 64 + t] = dww[(size_t)e * 576 + t * 9 + tap];
        lg[e] = g_logit[b][e];
    }
    __syncthreads();

    float acc[4];
#pragma unroll
    for (int cc = 0; cc < 4; cc++) acc[cc] = 0.f;

#pragma unroll
    for (int e = 0; e < 3; e++) {
        float l = lg[e];
        const float* P  = &PsT[e * 4160];
        const float* wd = &wds[e * 64];
        const float* M  = &M1s[e * 1024];
#pragma unroll 4
        for (int m = 0; m < 64; m++) {
            float coef = l * P[m * 65 + o] * wd[m];
            const float* mm = &M[m * 16 + cg];
#pragma unroll
            for (int cc = 0; cc < 4; cc++) acc[cc] = fmaf(coef, mm[cc], acc[cc]);
        }
    }
    uint16_t* bh = &g_Bt[b][tap][0];
#pragma unroll
    for (int cc = 0; cc < 4; cc++) {
        int c = z * 16 + cg + cc;
        bh[o * 64 + c] = __half_as_ushort(__float2half_rn(acc[cc] * B_SCALE));
    }
}

// =========================================================================
// K5: warp-MMA conv — single-term fp16 (A fp16, B fp16 hi, scaled).
//     Block = 2 image rows (256 px) x 64 oc; 8 warps, warp tile 32x64.
//     grid (64, 8), 256 threads, dyn smem ~82 KB -> 2 blocks/SM.
// =========================================================================
__global__ __launch_bounds__(256, 2) void k_convmma(const float* __restrict__ x,
                                                    float* __restrict__ out) {
    extern __shared__ __align__(16) char smem[];
    uint16_t* Th = reinterpret_cast<uint16_t*>(smem);
    const uint32_t* Twh = reinterpret_cast<const uint32_t*>(smem);
    uint32_t* Bs = reinterpret_cast<uint32_t*>(smem + BS_OFF);

    const int tid = threadIdx.x;
    const int b = blockIdx.y;
    const int y0 = blockIdx.x * 2;

    const uint32_t* Bg = reinterpret_cast<const uint32_t*>(&g_Bt[b][0][0]);
    uint32_t breg[8];
#pragma unroll
    for (int i = 0; i < 8; i++) breg[i] = __ldg(&Bg[tid + i * 256]);   // tap 0

    // stage x rows y0-1..y0+2, px -1..128, 64 ch as a single fp16 plane
    const float* xb = x + (size_t)b * 64 * HWN;
    for (int idx = tid; idx < 4 * 130 * 64; idx += 256) {
        int p = idx % 130;
        int rest = idx / 130;
        int c = rest & 63, ri = rest >> 6;
        int gr = y0 - 1 + ri, gp = p - 1;
        float v = 0.f;
        if ((unsigned)gr < 128u && (unsigned)gp < 128u)
            v = __ldg(&xb[(size_t)c * HWN + gr * 128 + gp]);
        Th[(ri * 130 + p) * 72 + c] = __half_as_ushort(__float2half_rn(v));
    }

    const int w = tid >> 5, lane = tid & 31;
    const int g = lane >> 2, tg = lane & 3;
    const int wrow = w >> 2, wcol = (w & 3) * 32;

    float acc[2][8][4];
#pragma unroll
    for (int s = 0; s < 2; s++)
#pragma unroll
        for (int j = 0; j < 8; j++)
#pragma unroll
            for (int r = 0; r < 4; r++) acc[s][j][r] = 0.f;

    for (int tap = 0; tap < 9; tap++) {
        int dy = tap / 3, dx = tap % 3;
        __syncthreads();   // T staged (tap 0) / prev tap's Bs consumed
        {   // store prefetched B regs -> Bs
#pragma unroll
            for (int i = 0; i < 8; i++) {
                int idx = tid + i * 256;           // 0..2047
                int row = idx >> 5, u = idx & 31;
                Bs[row * TW_STRIDE + u] = breg[i];
            }
        }
        __syncthreads();
        if (tap < 8) {      // prefetch next tap (hides LDG under MMA)
#pragma unroll
            for (int i = 0; i < 8; i++)
                breg[i] = __ldg(&Bg[(size_t)(tap + 1) * 2048 + tid + i * 256]);
        }

        int ri0 = wrow + dy;
#pragma unroll
        for (int kc = 0; kc < 4; kc++) {
            uint32_t ahi[2][4];
#pragma unroll
            for (int s = 0; s < 2; s++) {
                int p0 = wcol + s * 16 + g + dx;
                int w0 = (ri0 * 130 + p0) * TW_STRIDE + kc * 8 + tg;
                ahi[s][0] = Twh[w0];       ahi[s][1] = Twh[w0 + 8 * TW_STRIDE];
                ahi[s][2] = Twh[w0 + 4];   ahi[s][3] = Twh[w0 + 8 * TW_STRIDE + 4];
            }
#pragma unroll
            for (int j = 0; j < 8; j++) {
                int bw = (j * 8 + g) * TW_STRIDE + kc * 8 + tg;
                uint32_t bh0 = Bs[bw], bh1 = Bs[bw + 4];
#pragma unroll
                for (int s = 0; s < 2; s++)
                    mma_f16(acc[s][j], ahi[s], bh0, bh1);
            }
        }
    }
    __syncthreads();   // all warps done reading T -> reuse as Ds

    // scatter accs (undoing the B_SCALE) to Ds[oc][px]
    float* Ds = reinterpret_cast<float*>(smem);
#pragma unroll
    for (int s = 0; s < 2; s++) {
        int px = wrow * 128 + wcol + s * 16 + g;
#pragma unroll
        for (int j = 0; j < 8; j++) {
            int oc = j * 8 + tg * 2;
            Ds[oc * DS_STRIDE + px]           = acc[s][j][0] * B_INV;
            Ds[(oc + 1) * DS_STRIDE + px]     = acc[s][j][1] * B_INV;
            Ds[oc * DS_STRIDE + px + 8]       = acc[s][j][2] * B_INV;
            Ds[(oc + 1) * DS_STRIDE + px + 8] = acc[s][j][3] * B_INV;
        }
    }
    __syncthreads();

    float* ob = out + (size_t)b * 64 * HWN;
#pragma unroll
    for (int i = 0; i < 16; i++) {
        int idx = tid + i * 256;
        int oc = idx >> 6, f4 = idx & 63;
        int px = f4 * 4;
        float4 v = *reinterpret_cast<const float4*>(&Ds[oc * DS_STRIDE + px]);
        int yy = y0 + (px >> 7), xx = px & 127;
        *reinterpret_cast<float4*>(&ob[((size_t)oc * 128 + yy) * 128 + xx]) = v;
    }
}

// =========================================================================
extern "C" void kernel_launch(void* const* d_in, const int* in_sizes, int n_in,
                              void* d_out, int out_size) {
    const float* x      = (const float*)d_in[0];
    const float* hidden = (const float*)d_in[1];
    const float* qkvw   = (const float*)d_in[2];
    const float* dww    = (const float*)d_in[3];
    const float* projw  = (const float*)d_in[4];
    const float* temp   = (const float*)d_in[5];
    const float* r1w    = (const float*)d_in[6];
    const float* r1b    = (const float*)d_in[7];
    const float* r3w    = (const float*)d_in[8];
    const float* r3b    = (const float*)d_in[9];
    float* out = (float*)d_out;

    cudaFuncSetAttribute(k_gram, cudaFuncAttributeMaxDynamicSharedMemorySize, GSM_TOTAL);
    cudaFuncSetAttribute(k_buildR, cudaFuncAttributeMaxDynamicSharedMemorySize, BR_SMEM);
    cudaFuncSetAttribute(k_convmma, cudaFuncAttributeMaxDynamicSharedMemorySize, SM_TOTAL);

    k_gram<<<dim3(16, 8), 256, GSM_TOTAL>>>(x);
    k_route<<<dim3(17, 8), 256>>>(hidden, r1w, r1b, r3w, r3b, out, out_size);
    k_attn<<<dim3(3, 8, 4), 256>>>(qkvw, temp);
    k_buildR<<<dim3(9, 8, 4), 256, BR_SMEM>>>(projw, dww);
    k_convmma<<<dim3(64, 8), 256, SM_TOTAL>>>(x, out);
}